// round 11
// baseline (speedup 1.0000x reference)
#include <cuda_runtime.h>
#include <cstdint>
#include <cstddef>

// ============================================================================
// Problem constants
// ============================================================================
static constexpr int BB  = 16;
static constexpr int SQ  = 2048;
static constexpr int DD  = 128;
static constexpr float QK_SCALE = 0.08838834764831845f;  // 1/sqrt(128)

// SMEM layout (bytes), 1 CTA/SM, 256 threads:
// Q : 128 rows x 128 words, pair-permuted + swizzled (64 KB), staged once
// K : double-buffered 64 kpos x 128 d word tiles (32 KB each)
// V : double-buffered 64 kpos x 128 d word tiles, swizzled (32 KB each)
// M : double-buffered mask tiles, 128 rows x 64 byte-cols, 80B pitch
static constexpr int OFF_Q  = 0;
static constexpr int OFF_K  = 65536;     // + p*32768
static constexpr int OFF_V  = 131072;    // + p*32768
static constexpr int OFF_M  = 196608;    // + p*10240
static constexpr int M_PITCH = 80;
static constexpr int SMEM_TOTAL = OFF_M + 2 * 10240;   // 217088 B

// ============================================================================
// Device globals: pre-converted tf32 K/V in tile-ready layouts (no cudaMalloc)
// ============================================================================
__device__ uint32_t g_K[(size_t)BB * SQ * DD];   // [kpos][d] pair-perm + swizzle
__device__ uint32_t g_V[(size_t)BB * SQ * DD];   // [kpos][d] swizzle

// ============================================================================
// Helpers
// ============================================================================
__device__ __forceinline__ uint32_t smem_u32(const void* p) {
    uint32_t a;
    asm("{ .reg .u64 t; cvta.to.shared.u64 t, %1; cvt.u32.u64 %0, t; }"
        : "=r"(a) : "l"(p));
    return a;
}

__device__ __forceinline__ uint32_t f2tf32(float f) {
    uint32_t r;
    asm("cvt.rna.tf32.f32 %0, %1;" : "=r"(r) : "f"(f));
    return r;
}

__device__ __forceinline__ void cp16(uint32_t dst, const void* src) {
    asm volatile("cp.async.cg.shared.global [%0], [%1], 16;"
                 :: "r"(dst), "l"(src) : "memory");
}
#define CP_COMMIT() asm volatile("cp.async.commit_group;" ::: "memory")
#define CP_WAIT0()  asm volatile("cp.async.wait_group 0;" ::: "memory")

__device__ __forceinline__ void mma_tf32(float& c0, float& c1, float& c2, float& c3,
                                         uint32_t a0, uint32_t a1, uint32_t a2, uint32_t a3,
                                         uint32_t b0, uint32_t b1) {
    asm volatile(
        "mma.sync.aligned.m16n8k8.row.col.f32.tf32.tf32.f32 "
        "{%0,%1,%2,%3}, {%4,%5,%6,%7}, {%8,%9}, {%0,%1,%2,%3};"
        : "+f"(c0), "+f"(c1), "+f"(c2), "+f"(c3)
        : "r"(a0), "r"(a1), "r"(a2), "r"(a3), "r"(b0), "r"(b1));
}

// ============================================================================
// Kernel 0: K/V fp32 -> tf32 pre-conversion, tile-ready layouts.
// K: word = kpos*128 + (pp(c) ^ ((kpos&3)<<3)), pp per-8-group (0,4,1,5,2,6,3,7)
//    so (t, t+4) fragment pairs are adjacent -> LDS.64.
// V: word = kpos*128 + (c ^ ((kpos&3)<<3))
// grid (512, 2), 256 threads; each block converts 8192 words.
// ============================================================================
__global__ void __launch_bounds__(256)
cvt_kernel(const float* __restrict__ Kg, const float* __restrict__ Vg) {
    const int tid = threadIdx.x;
    const size_t base = (size_t)blockIdx.x * 8192;
    if (blockIdx.y == 1) {
        #pragma unroll
        for (int i = 0; i < 8; i++) {
            uint32_t w = (tid + i * 256) * 4;               // word offset in block
            uint32_t r = (w >> 7) & 3;                      // kpos & 3
            uint32_t dcol = w & 127;
            uint32_t gL = (((dcol >> 3) ^ r) << 3);         // logical 8-col group
            const float* src = Kg + base + (w & ~127u) + gL;
            uint4 o;
            if (((dcol >> 2) & 1) == 0) {
                o.x = f2tf32(src[0]); o.y = f2tf32(src[4]);
                o.z = f2tf32(src[1]); o.w = f2tf32(src[5]);
            } else {
                o.x = f2tf32(src[2]); o.y = f2tf32(src[6]);
                o.z = f2tf32(src[3]); o.w = f2tf32(src[7]);
            }
            *(uint4*)(g_K + base + w) = o;
        }
    } else {
        #pragma unroll
        for (int i = 0; i < 8; i++) {
            uint32_t w = (tid + i * 256) * 4;
            uint32_t r = (w >> 7) & 3;                      // kpos & 3
            float4 v = *(const float4*)(Vg + base + w);
            uint4 o;
            o.x = f2tf32(v.x); o.y = f2tf32(v.y); o.z = f2tf32(v.z); o.w = f2tf32(v.w);
            uint32_t c = w & 127;
            *(uint4*)(g_V + base + (w & ~127u) + (c ^ (r << 3))) = o;
        }
    }
}

// ============================================================================
// Kernel A: flash attention. grid = (SQ/128, BB), 256 threads (8 warps).
// Warp owns 16 q-rows; 32 k-tiles of 64 kpos, cp.async double-buffered from
// pre-converted scratch. QK fragments via LDS.64. Fuses attn normalization.
// ============================================================================
__global__ void __launch_bounds__(256, 1)
attn_kernel(const float* __restrict__ Qg, const void* __restrict__ maskg,
            float* __restrict__ outg, float* __restrict__ attng, int has_attn) {
    extern __shared__ char smem[];
    const uint32_t sb = smem_u32(smem);
    uint32_t* const Qs = (uint32_t*)(smem + OFF_Q);

    const int tid = threadIdx.x, wid = tid >> 5, lane = tid & 31;
    const int g = lane >> 2, t = lane & 3;          // mma groupID / threadID
    const int qt = blockIdx.x, b = blockIdx.y;

    // ---- inline mask dtype detection (bool/uint8 vs int32) ----
    int bad = 0;
    { uint32_t w = ((const uint32_t*)maskg)[tid]; if (w & 0xffffff00u) bad = 1; }
    const int m32 = __syncthreads_or(bad) ? 0 : 1;

    const size_t mask_row0 = (size_t)(b * SQ + qt * 128);

    // ---- cp.async prefetch of tile kt into parity p (pure linear copies) ----
    auto issue_prefetch = [&](int kt, int p) {
        const size_t tbase = ((size_t)b * 32 + kt) * 8192;   // words
        const char* ksrc = (const char*)(g_K + tbase);
        const char* vsrc = (const char*)(g_V + tbase);
        const uint32_t kb = sb + OFF_K + p * 32768;
        const uint32_t vb = sb + OFF_V + p * 32768;
        #pragma unroll
        for (int j = 0; j < 8; j++) {
            int ci = tid + j * 256;                  // 2048 16B-chunks per tensor
            cp16(kb + ci * 16, ksrc + ci * 16);
            cp16(vb + ci * 16, vsrc + ci * 16);
        }
        if (!m32) {
            const uint8_t* msrc = (const uint8_t*)maskg + mask_row0 * SQ + (size_t)kt * 64;
            const uint32_t mb = sb + OFF_M + p * 10240;
            #pragma unroll
            for (int j = 0; j < 2; j++) {
                int ci = tid + j * 256;              // 512 chunks: 128 rows x 4
                int r = ci >> 2, q = ci & 3;
                cp16(mb + r * M_PITCH + q * 16, msrc + (size_t)r * SQ + q * 16);
            }
        }
        CP_COMMIT();
    };
    issue_prefetch(0, 0);

    // ---- stage Q (128x128), pair-permuted + swizzled, fp32 -> tf32 ----
    {
        const float* qsrc = Qg + ((size_t)(b * SQ + qt * 128)) * DD;
        #pragma unroll
        for (int i = 0; i < 16; i++) {
            int idx = tid + i * 256;
            int r = idx >> 5, f = idx & 31;
            float4 v = ((const float4*)(qsrc + (size_t)r * DD))[f];
            uint32_t xr = (r & 3) << 3;
            #pragma unroll
            for (int j = 0; j < 4; j++) {
                int c = 4 * f + j;
                uint32_t pp = (c & ~7) | ((c & 3) << 1) | ((c >> 2) & 1);
                Qs[r * 128 + (pp ^ xr)] = f2tf32(((const float*)&v)[j]);
            }
        }
    }

    // persistent accumulators: O tile (16 rows x 128 d per warp) + rowsums
    float o[16][4];
    #pragma unroll
    for (int nt = 0; nt < 16; nt++) { o[nt][0] = o[nt][1] = o[nt][2] = o[nt][3] = 0.0f; }
    float lsum0 = 0.0f, lsum1 = 0.0f;

    const int qb = wid * 16;                               // CTA-local row base
    const size_t qrow_g = (size_t)(b * SQ + qt * 128) + qb + g;

    const int srcA = (lane & 0x1C) | ((lane & 3) >> 1);    // C->A frag shuffle srcs
    const int srcB = srcA + 2;
    const bool sel = lane & 1;
    const uint32_t xg = (g & 3) << 3;

    for (int kt = 0; kt < 32; kt++) {                      // FIX: 32 tiles (was 16)
        const int p = kt & 1;
        uint32_t* const Ks = (uint32_t*)(smem + OFF_K + p * 32768);
        uint32_t* const Vs = (uint32_t*)(smem + OFF_V + p * 32768);
        uint8_t*  const Ms = (uint8_t*)(smem + OFF_M + p * 10240);

        CP_WAIT0();
        __syncthreads();

        // ---- int32 mask fallback: manual stage (packed to bytes) ----
        if (m32) {
            const int* msrc = (const int*)maskg;
            #pragma unroll
            for (int i = 0; i < 8; i++) {
                int lin = tid + i * 256;               // 2048 groups of 4 ints
                int r = lin >> 4, gi = lin & 15;
                size_t off = (mask_row0 + r) * SQ + kt * 64 + 4 * gi;
                uint4 x = *(const uint4*)(msrc + off);
                uint32_t packed = (x.x & 0xffu) | ((x.y & 0xffu) << 8) |
                                  ((x.z & 0xffu) << 16) | ((x.w & 0xffu) << 24);
                *(uint32_t*)(Ms + r * M_PITCH + 4 * gi) = packed;
            }
            __syncthreads();
        }
        if (kt < 31) issue_prefetch(kt + 1, p ^ 1);        // FIX: guard 31 (was 15)

        // ---- QK^T: scores C (16 rows x 64 kpos per warp), LDS.64 frags ----
        float c[8][4];
        #pragma unroll
        for (int nt = 0; nt < 8; nt++) { c[nt][0] = c[nt][1] = c[nt][2] = c[nt][3] = 0.0f; }

        #pragma unroll
        for (int ks = 0; ks < 16; ks++) {
            const uint32_t pc = ((uint32_t)(8 * ks + 2 * t)) ^ xg;
            const uint2 a01 = *(const uint2*)(Qs + (qb + g) * 128 + pc);
            const uint2 a23 = *(const uint2*)(Qs + (qb + 8 + g) * 128 + pc);
            #pragma unroll
            for (int nt = 0; nt < 8; nt++) {
                const uint2 bb = *(const uint2*)(Ks + (8 * nt + g) * 128 + pc);
                mma_tf32(c[nt][0], c[nt][1], c[nt][2], c[nt][3],
                         a01.x, a23.x, a01.y, a23.y, bb.x, bb.y);
            }
        }

        // ---- softmax numerator: mask, exp, rowsum, attn write ----
        float* arow0 = attng + qrow_g * SQ + kt * 64;
        float* arow1 = arow0 + 8 * (size_t)SQ;
        const uint8_t* mrow0 = Ms + (qb + g) * M_PITCH;
        const uint8_t* mrow1 = Ms + (qb + 8 + g) * M_PITCH;
        #pragma unroll
        for (int nt = 0; nt < 8; nt++) {
            const int cb = 8 * nt + 2 * t;
            uint32_t m0 = *(const uint16_t*)(mrow0 + cb);
            uint32_t m1 = *(const uint16_t*)(mrow1 + cb);
            float e0 = (m0 & 0xffu) ? 0.0f : __expf(c[nt][0] * QK_SCALE);
            float e1 = (m0 >> 8)    ? 0.0f : __expf(c[nt][1] * QK_SCALE);
            float e2 = (m1 & 0xffu) ? 0.0f : __expf(c[nt][2] * QK_SCALE);
            float e3 = (m1 >> 8)    ? 0.0f : __expf(c[nt][3] * QK_SCALE);
            c[nt][0] = e0; c[nt][1] = e1; c[nt][2] = e2; c[nt][3] = e3;
            lsum0 += e0 + e1;
            lsum1 += e2 + e3;
            if (has_attn) {
                __stcs((float2*)(arow0 + cb), make_float2(e0, e1));
                __stcs((float2*)(arow1 + cb), make_float2(e2, e3));
            }
        }

        // ---- PV: O += E @ V. C-frag(ks2) -> A-frag via shuffles; B loads
        //      from [kpos][d] swizzled V tile. ----
        #pragma unroll
        for (int ks2 = 0; ks2 < 8; ks2++) {
            float v00 = __shfl_sync(0xffffffffu, c[ks2][0], srcA);
            float v01 = __shfl_sync(0xffffffffu, c[ks2][1], srcA);
            float v20 = __shfl_sync(0xffffffffu, c[ks2][2], srcA);
            float v21 = __shfl_sync(0xffffffffu, c[ks2][3], srcA);
            float w00 = __shfl_sync(0xffffffffu, c[ks2][0], srcB);
            float w01 = __shfl_sync(0xffffffffu, c[ks2][1], srcB);
            float w20 = __shfl_sync(0xffffffffu, c[ks2][2], srcB);
            float w21 = __shfl_sync(0xffffffffu, c[ks2][3], srcB);
            const uint32_t a0 = f2tf32(sel ? v01 : v00);
            const uint32_t a1 = f2tf32(sel ? v21 : v20);
            const uint32_t a2 = f2tf32(sel ? w01 : w00);
            const uint32_t a3 = f2tf32(sel ? w21 : w20);
            const int vr0 = 8 * ks2 + t;
            const int vr4 = vr0 + 4;
            #pragma unroll
            for (int nt = 0; nt < 16; nt++) {
                const int cc = (8 * nt + g) ^ (t << 3);
                const uint32_t b0 = Vs[vr0 * 128 + cc];
                const uint32_t b1 = Vs[vr4 * 128 + cc];
                mma_tf32(o[nt][0], o[nt][1], o[nt][2], o[nt][3],
                         a0, a1, a2, a3, b0, b1);
            }
        }
    }

    // ---- reduce rowsums across the quad ----
    lsum0 += __shfl_xor_sync(0xffffffffu, lsum0, 1);
    lsum0 += __shfl_xor_sync(0xffffffffu, lsum0, 2);
    lsum1 += __shfl_xor_sync(0xffffffffu, lsum1, 1);
    lsum1 += __shfl_xor_sync(0xffffffffu, lsum1, 2);
    const float inv0 = 1.0f / lsum0;
    const float inv1 = 1.0f / lsum1;

    // share per-row inv via SMEM (K buffer p=0 is dead; last tile used p=1)
    float* sInv = (float*)(smem + OFF_K);
    __syncthreads();
    if (t == 0) {
        sInv[qb + g]     = inv0;
        sInv[qb + 8 + g] = inv1;
    }

    // ---- out = O / rowsum ----
    float* orow0 = outg + qrow_g * DD;
    float* orow1 = orow0 + 8 * (size_t)DD;
    #pragma unroll
    for (int nt = 0; nt < 16; nt++) {
        const int cb = 8 * nt + 2 * t;
        *(float2*)(orow0 + cb) = make_float2(o[nt][0] * inv0, o[nt][1] * inv0);
        *(float2*)(orow1 + cb) = make_float2(o[nt][2] * inv1, o[nt][3] * inv1);
    }

    // ---- fused normalization of this CTA's 128 attn rows ----
    if (has_attn) {
        __syncthreads();
        float4* ap = (float4*)attng + ((size_t)(b * SQ + qt * 128)) * 512;
        #pragma unroll 4
        for (int i = 0; i < 256; i++) {
            int idx = tid + i * 256;                  // 0..65535 float4
            int r = idx >> 9, cw = idx & 511;
            float inv = sInv[r];
            float4 v = __ldcs(ap + (size_t)r * 512 + cw);
            v.x *= inv; v.y *= inv; v.z *= inv; v.w *= inv;
            __stcs(ap + (size_t)r * 512 + cw, v);
        }
    }
}

// ============================================================================
// Launch
// ============================================================================
extern "C" void kernel_launch(void* const* d_in, const int* in_sizes, int n_in,
                              void* d_out, int out_size) {
    const float* Q = (const float*)d_in[0];
    const float* K = (const float*)d_in[1];
    const float* V = (const float*)d_in[2];
    const void*  M = d_in[3];

    float* out = (float*)d_out;
    const long long out_elems  = (long long)BB * SQ * DD;              // 4,194,304
    const long long attn_elems = (long long)BB * SQ * SQ;              // 67,108,864
    int has_attn = ((long long)out_size >= out_elems + attn_elems) ? 1 : 0;
    float* attn = has_attn ? (out + out_elems) : out;   // dummy ptr if unused

    cudaFuncSetAttribute(attn_kernel,
                         cudaFuncAttributeMaxDynamicSharedMemorySize, SMEM_TOTAL);

    cvt_kernel<<<dim3(512, 2), 256>>>(K, V);
    attn_kernel<<<dim3(SQ / 128, BB), 256, SMEM_TOTAL>>>(Q, M, out, attn, has_attn);
}

// round 12
// speedup vs baseline: 1.2780x; 1.2780x over previous
#include <cuda_runtime.h>
#include <cstdint>
#include <cstddef>

// ============================================================================
// Problem constants
// ============================================================================
static constexpr int BB  = 16;
static constexpr int SQ  = 2048;
static constexpr int DD  = 128;
static constexpr float QK_SCALE = 0.08838834764831845f;  // 1/sqrt(128)

// SMEM layout (bytes), 1 CTA/SM, 256 threads:
// Q : 128 rows x 128 words, swizzled c^((r&7)<<2) (64 KB), staged once
// K : double-buffered 64 kpos x 128 d word tiles, c^((kpos&7)<<2) (32 KB each)
// V : double-buffered 64 kpos x 128 d word tiles, c^((kpos&3)<<3) (32 KB each)
// M : double-buffered mask tiles, 128 rows x 64 byte-cols, 80B pitch
static constexpr int OFF_Q  = 0;
static constexpr int OFF_K  = 65536;     // + p*32768
static constexpr int OFF_V  = 131072;    // + p*32768
static constexpr int OFF_M  = 196608;    // + p*10240
static constexpr int M_PITCH = 80;
static constexpr int SMEM_TOTAL = OFF_M + 2 * 10240;   // 217088 B

// ============================================================================
// Device globals (no dynamic allocation allowed)
// ============================================================================
__device__ float    g_inv[BB * SQ];
__device__ uint32_t g_K[(size_t)BB * SQ * DD];   // tf32, tile-ready swizzle
__device__ uint32_t g_V[(size_t)BB * SQ * DD];   // tf32, tile-ready swizzle

// ============================================================================
// Helpers
// ============================================================================
__device__ __forceinline__ uint32_t smem_u32(const void* p) {
    uint32_t a;
    asm("{ .reg .u64 t; cvta.to.shared.u64 t, %1; cvt.u32.u64 %0, t; }"
        : "=r"(a) : "l"(p));
    return a;
}

__device__ __forceinline__ uint32_t f2tf32(float f) {
    uint32_t r;
    asm("cvt.rna.tf32.f32 %0, %1;" : "=r"(r) : "f"(f));
    return r;
}

__device__ __forceinline__ void cp16(uint32_t dst, const void* src) {
    asm volatile("cp.async.cg.shared.global [%0], [%1], 16;"
                 :: "r"(dst), "l"(src) : "memory");
}
#define CP_COMMIT() asm volatile("cp.async.commit_group;" ::: "memory")
#define CP_WAIT0()  asm volatile("cp.async.wait_group 0;" ::: "memory")

__device__ __forceinline__ void mma_tf32(float& c0, float& c1, float& c2, float& c3,
                                         uint32_t a0, uint32_t a1, uint32_t a2, uint32_t a3,
                                         uint32_t b0, uint32_t b1) {
    asm volatile(
        "mma.sync.aligned.m16n8k8.row.col.f32.tf32.tf32.f32 "
        "{%0,%1,%2,%3}, {%4,%5,%6,%7}, {%8,%9}, {%0,%1,%2,%3};"
        : "+f"(c0), "+f"(c1), "+f"(c2), "+f"(c3)
        : "r"(a0), "r"(a1), "r"(a2), "r"(a3), "r"(b0), "r"(b1));
}

// ============================================================================
// Kernel 0: K/V fp32 -> tf32 pre-conversion into the EXACT tile layouts the
// attention kernel's validated (R5) fragment loads expect:
//   K: word = kpos*128 + (c ^ ((kpos&7)<<2))
//   V: word = kpos*128 + (c ^ ((kpos&3)<<3))
// Gathered read (uint4-aligned since xor values are multiples of 4 words),
// linear write. grid (512, 2), 256 threads; 8192 words per block.
// ============================================================================
__global__ void __launch_bounds__(256)
cvt_kernel(const float* __restrict__ Kg, const float* __restrict__ Vg) {
    const int tid = threadIdx.x;
    const size_t base = (size_t)blockIdx.x * 8192;
    if (blockIdx.y == 1) {
        #pragma unroll
        for (int i = 0; i < 8; i++) {
            uint32_t w = (tid + i * 256) * 4;          // dest word offset in block
            uint32_t r7 = (w >> 7) & 7;                // kpos & 7
            uint32_t c = w & 127;
            const float* src = Kg + base + (w & ~127u) + (c ^ (r7 << 2));
            float4 v = *(const float4*)src;
            uint4 o;
            o.x = f2tf32(v.x); o.y = f2tf32(v.y); o.z = f2tf32(v.z); o.w = f2tf32(v.w);
            *(uint4*)(g_K + base + w) = o;
        }
    } else {
        #pragma unroll
        for (int i = 0; i < 8; i++) {
            uint32_t w = (tid + i * 256) * 4;
            uint32_t r3 = (w >> 7) & 3;                // kpos & 3
            uint32_t c = w & 127;
            const float* src = Vg + base + (w & ~127u) + (c ^ (r3 << 3));
            float4 v = *(const float4*)src;
            uint4 o;
            o.x = f2tf32(v.x); o.y = f2tf32(v.y); o.z = f2tf32(v.z); o.w = f2tf32(v.w);
            *(uint4*)(g_V + base + w) = o;
        }
    }
}

// ============================================================================
// Kernel A: flash attention. grid = (SQ/128, BB), 256 threads (8 warps).
// Warp owns 16 q-rows; 32 k-tiles of 64 kpos, cp.async double-buffered
// LINEARLY from pre-converted scratch (no per-tile conversion pass; one
// barrier per tile on the byte-mask path). Compute identical to the
// measured-best R5 kernel. Writes UNNORMALIZED exp(scores) to attn,
// out = (E@V)/rowsum, 1/rowsum -> g_inv.
// ============================================================================
__global__ void __launch_bounds__(256, 1)
attn_kernel(const float* __restrict__ Qg, const void* __restrict__ maskg,
            float* __restrict__ outg, float* __restrict__ attng, int has_attn) {
    extern __shared__ char smem[];
    const uint32_t sb = smem_u32(smem);
    uint32_t* const Qs = (uint32_t*)(smem + OFF_Q);

    const int tid = threadIdx.x, wid = tid >> 5, lane = tid & 31;
    const int g = lane >> 2, t = lane & 3;          // mma groupID / threadID
    const int qt = blockIdx.x, b = blockIdx.y;

    // ---- inline mask dtype detection (bool/uint8 vs int32) ----
    int bad = 0;
    { uint32_t w = ((const uint32_t*)maskg)[tid]; if (w & 0xffffff00u) bad = 1; }
    const int m32 = __syncthreads_or(bad) ? 0 : 1;

    const size_t mask_row0 = (size_t)(b * SQ + qt * 128);

    // ---- cp.async prefetch of tile kt into parity p (pure linear copies) ----
    auto issue_prefetch = [&](int kt, int p) {
        const size_t tbase = ((size_t)b * 32 + kt) * 8192;   // words
        const char* ksrc = (const char*)(g_K + tbase);
        const char* vsrc = (const char*)(g_V + tbase);
        const uint32_t kb = sb + OFF_K + p * 32768;
        const uint32_t vb = sb + OFF_V + p * 32768;
        #pragma unroll
        for (int j = 0; j < 8; j++) {
            int ci = tid + j * 256;                  // 2048 16B-chunks per tensor
            cp16(kb + ci * 16, ksrc + ci * 16);
            cp16(vb + ci * 16, vsrc + ci * 16);
        }
        if (!m32) {
            const uint8_t* msrc = (const uint8_t*)maskg + mask_row0 * SQ + (size_t)kt * 64;
            const uint32_t mb = sb + OFF_M + p * 10240;
            #pragma unroll
            for (int j = 0; j < 2; j++) {
                int ci = tid + j * 256;              // 512 chunks: 128 rows x 4
                int r = ci >> 2, q = ci & 3;
                cp16(mb + r * M_PITCH + q * 16, msrc + (size_t)r * SQ + q * 16);
            }
        }
        CP_COMMIT();
    };
    issue_prefetch(0, 0);

    // ---- stage Q once (fp32 -> tf32, swizzle c ^ ((r&7)<<2)) ----
    {
        const float* qsrc = Qg + ((size_t)(b * SQ + qt * 128)) * DD;
        #pragma unroll
        for (int i = 0; i < 16; i++) {
            int idx = tid + i * 256;
            int r = idx >> 5, f = idx & 31, c = f * 4;
            float4 v = ((const float4*)(qsrc + (size_t)r * DD))[f];
            uint4 w;
            w.x = f2tf32(v.x); w.y = f2tf32(v.y); w.z = f2tf32(v.z); w.w = f2tf32(v.w);
            *(uint4*)(Qs + r * 128 + (c ^ ((r & 7) << 2))) = w;
        }
    }

    // persistent accumulators: O tile (16 rows x 128 d per warp) + rowsums
    float o[16][4];
    #pragma unroll
    for (int nt = 0; nt < 16; nt++) { o[nt][0] = o[nt][1] = o[nt][2] = o[nt][3] = 0.0f; }
    float lsum0 = 0.0f, lsum1 = 0.0f;

    const int qrow_l = wid * 16 + g;                       // CTA-local query row
    const size_t qrow_g = (size_t)(b * SQ + qt * 128) + qrow_l;

    const int srcA = (lane & 0x1C) | ((lane & 3) >> 1);    // C->A frag shuffle srcs
    const int srcB = srcA + 2;
    const bool sel = lane & 1;

    for (int kt = 0; kt < 32; kt++) {
        const int p = kt & 1;
        uint32_t* const Ks = (uint32_t*)(smem + OFF_K + p * 32768);
        uint32_t* const Vs = (uint32_t*)(smem + OFF_V + p * 32768);
        uint8_t*  const Ms = (uint8_t*)(smem + OFF_M + p * 10240);

        CP_WAIT0();
        __syncthreads();   // tile kt landed; all warps done with buffer p^1

        // prefetch next tile into the other buffers (overlaps compute)
        if (kt < 31) issue_prefetch(kt + 1, p ^ 1);

        // ---- int32 mask fallback: manual stage (packed to bytes) ----
        if (m32) {
            const int* msrc = (const int*)maskg;
            #pragma unroll
            for (int i = 0; i < 8; i++) {
                int lin = tid + i * 256;               // 2048 groups of 4 ints
                int r = lin >> 4, gi = lin & 15;
                size_t off = (mask_row0 + r) * SQ + kt * 64 + 4 * gi;
                uint4 x = *(const uint4*)(msrc + off);
                uint32_t packed = (x.x & 0xffu) | ((x.y & 0xffu) << 8) |
                                  ((x.z & 0xffu) << 16) | ((x.w & 0xffu) << 24);
                *(uint32_t*)(Ms + r * M_PITCH + 4 * gi) = packed;
            }
            __syncthreads();
        }

        // ---- QK^T: scores C (16 rows x 64 kpos per warp) ----
        float c[8][4];
        #pragma unroll
        for (int nt = 0; nt < 8; nt++) { c[nt][0] = c[nt][1] = c[nt][2] = c[nt][3] = 0.0f; }

        #pragma unroll
        for (int ks = 0; ks < 16; ks++) {
            const int col0 = (8 * ks + t) ^ (g << 2);
            const int col4 = (8 * ks + 4 + t) ^ (g << 2);
            const uint32_t a0 = Qs[qrow_l * 128 + col0];
            const uint32_t a1 = Qs[(qrow_l + 8) * 128 + col0];
            const uint32_t a2 = Qs[qrow_l * 128 + col4];
            const uint32_t a3 = Qs[(qrow_l + 8) * 128 + col4];
            #pragma unroll
            for (int nt = 0; nt < 8; nt++) {
                const int kr = 8 * nt + g;
                const uint32_t b0 = Ks[kr * 128 + col0];
                const uint32_t b1 = Ks[kr * 128 + col4];
                mma_tf32(c[nt][0], c[nt][1], c[nt][2], c[nt][3], a0, a1, a2, a3, b0, b1);
            }
        }

        // ---- softmax numerator: mask, exp, rowsum, attn write ----
        float* arow0 = attng + qrow_g * SQ + kt * 64;
        float* arow1 = arow0 + 8 * (size_t)SQ;
        const uint8_t* mrow0 = Ms + qrow_l * M_PITCH;
        const uint8_t* mrow1 = Ms + (qrow_l + 8) * M_PITCH;
        #pragma unroll
        for (int nt = 0; nt < 8; nt++) {
            const int cb = 8 * nt + 2 * t;
            uint32_t m0 = *(const uint16_t*)(mrow0 + cb);
            uint32_t m1 = *(const uint16_t*)(mrow1 + cb);
            float e0 = (m0 & 0xffu) ? 0.0f : __expf(c[nt][0] * QK_SCALE);
            float e1 = (m0 >> 8)    ? 0.0f : __expf(c[nt][1] * QK_SCALE);
            float e2 = (m1 & 0xffu) ? 0.0f : __expf(c[nt][2] * QK_SCALE);
            float e3 = (m1 >> 8)    ? 0.0f : __expf(c[nt][3] * QK_SCALE);
            c[nt][0] = e0; c[nt][1] = e1; c[nt][2] = e2; c[nt][3] = e3;
            lsum0 += e0 + e1;
            lsum1 += e2 + e3;
            if (has_attn) {
                __stcs((float2*)(arow0 + cb), make_float2(e0, e1));
                __stcs((float2*)(arow1 + cb), make_float2(e2, e3));
            }
        }

        // ---- PV: O += E @ V. C-frag(ks2) -> A-frag via shuffles. ----
        #pragma unroll
        for (int ks2 = 0; ks2 < 8; ks2++) {
            float v00 = __shfl_sync(0xffffffffu, c[ks2][0], srcA);
            float v01 = __shfl_sync(0xffffffffu, c[ks2][1], srcA);
            float v20 = __shfl_sync(0xffffffffu, c[ks2][2], srcA);
            float v21 = __shfl_sync(0xffffffffu, c[ks2][3], srcA);
            float w00 = __shfl_sync(0xffffffffu, c[ks2][0], srcB);
            float w01 = __shfl_sync(0xffffffffu, c[ks2][1], srcB);
            float w20 = __shfl_sync(0xffffffffu, c[ks2][2], srcB);
            float w21 = __shfl_sync(0xffffffffu, c[ks2][3], srcB);
            const uint32_t a0 = f2tf32(sel ? v01 : v00);
            const uint32_t a1 = f2tf32(sel ? v21 : v20);
            const uint32_t a2 = f2tf32(sel ? w01 : w00);
            const uint32_t a3 = f2tf32(sel ? w21 : w20);
            const int vr0 = 8 * ks2 + t;
            const int vr4 = vr0 + 4;
            #pragma unroll
            for (int nt = 0; nt < 16; nt++) {
                const int cc = (8 * nt + g) ^ (t << 3);
                const uint32_t b0 = Vs[vr0 * 128 + cc];
                const uint32_t b1 = Vs[vr4 * 128 + cc];
                mma_tf32(o[nt][0], o[nt][1], o[nt][2], o[nt][3],
                         a0, a1, a2, a3, b0, b1);
            }
        }
    }

    // ---- reduce rowsums across the quad ----
    lsum0 += __shfl_xor_sync(0xffffffffu, lsum0, 1);
    lsum0 += __shfl_xor_sync(0xffffffffu, lsum0, 2);
    lsum1 += __shfl_xor_sync(0xffffffffu, lsum1, 1);
    lsum1 += __shfl_xor_sync(0xffffffffu, lsum1, 2);
    const float inv0 = 1.0f / lsum0;
    const float inv1 = 1.0f / lsum1;
    if (t == 0) {
        g_inv[qrow_g]     = inv0;
        g_inv[qrow_g + 8] = inv1;
    }

    // ---- out = O / rowsum ----
    float* orow0 = outg + qrow_g * DD;
    float* orow1 = orow0 + 8 * (size_t)DD;
    #pragma unroll
    for (int nt = 0; nt < 16; nt++) {
        const int cb = 8 * nt + 2 * t;
        *(float2*)(orow0 + cb) = make_float2(o[nt][0] * inv0, o[nt][1] * inv0);
        *(float2*)(orow1 + cb) = make_float2(o[nt][2] * inv1, o[nt][3] * inv1);
    }
}

// ============================================================================
// Kernel B: attn[i] *= 1/rowsum (float4 grid-stride) — measured 75us @80% DRAM
// ============================================================================
__global__ void __launch_bounds__(256)
norm_kernel(float* __restrict__ attn) {
    const size_t n4 = (size_t)BB * SQ * SQ / 4;       // 16,777,216 float4
    const size_t stride = (size_t)gridDim.x * 256;
    for (size_t i = (size_t)blockIdx.x * 256 + threadIdx.x; i < n4; i += stride) {
        float inv = g_inv[i >> 9];                     // 512 float4 per row
        float4 v = ((const float4*)attn)[i];
        v.x *= inv; v.y *= inv; v.z *= inv; v.w *= inv;
        ((float4*)attn)[i] = v;
    }
}

// ============================================================================
// Launch
// ============================================================================
extern "C" void kernel_launch(void* const* d_in, const int* in_sizes, int n_in,
                              void* d_out, int out_size) {
    const float* Q = (const float*)d_in[0];
    const float* K = (const float*)d_in[1];
    const float* V = (const float*)d_in[2];
    const void*  M = d_in[3];

    float* out = (float*)d_out;
    const long long out_elems  = (long long)BB * SQ * DD;              // 4,194,304
    const long long attn_elems = (long long)BB * SQ * SQ;              // 67,108,864
    int has_attn = ((long long)out_size >= out_elems + attn_elems) ? 1 : 0;
    float* attn = has_attn ? (out + out_elems) : out;   // dummy ptr if unused

    cudaFuncSetAttribute(attn_kernel,
                         cudaFuncAttributeMaxDynamicSharedMemorySize, SMEM_TOTAL);

    cvt_kernel<<<dim3(512, 2), 256>>>(K, V);
    attn_kernel<<<dim3(SQ / 128, BB), 256, SMEM_TOTAL>>>(Q, M, out, attn, has_attn);
    if (has_attn)
        norm_kernel<<<8192, 256>>>(attn);
}

// round 13
// speedup vs baseline: 1.4077x; 1.1014x over previous
#include <cuda_runtime.h>
#include <cstdint>
#include <cstddef>

// ============================================================================
// Problem constants
// ============================================================================
static constexpr int BB  = 16;
static constexpr int SQ  = 2048;
static constexpr int DD  = 128;
static constexpr float QK_SCALE = 0.08838834764831845f;  // 1/sqrt(128)

// SMEM layout (bytes), 1 CTA/SM, 256 threads:
// Q : 128 rows x 128 words, pair-permuted + swizzled (64 KB), staged once
// K : double-buffered 64 kpos x 128 d word tiles, pp + swizzle (32 KB each)
// V : double-buffered 64 kpos x 128 d word tiles, c^((kpos&3)<<3) (32 KB each)
// M : double-buffered mask tiles, 128 rows x 64 byte-cols, 80B pitch
static constexpr int OFF_Q  = 0;
static constexpr int OFF_K  = 65536;     // + p*32768
static constexpr int OFF_V  = 131072;    // + p*32768
static constexpr int OFF_M  = 196608;    // + p*10240
static constexpr int M_PITCH = 80;
static constexpr int SMEM_TOTAL = OFF_M + 2 * 10240;   // 217088 B

// ============================================================================
// Device globals (no dynamic allocation allowed)
// ============================================================================
__device__ float    g_inv[BB * SQ];
__device__ uint32_t g_K[(size_t)BB * SQ * DD];   // tf32 [kpos][d], pp + swizzle
__device__ uint32_t g_V[(size_t)BB * SQ * DD];   // tf32 [kpos][d], swizzle

// ============================================================================
// Helpers
// ============================================================================
__device__ __forceinline__ uint32_t smem_u32(const void* p) {
    uint32_t a;
    asm("{ .reg .u64 t; cvta.to.shared.u64 t, %1; cvt.u32.u64 %0, t; }"
        : "=r"(a) : "l"(p));
    return a;
}

__device__ __forceinline__ uint32_t f2tf32(float f) {
    uint32_t r;
    asm("cvt.rna.tf32.f32 %0, %1;" : "=r"(r) : "f"(f));
    return r;
}

__device__ __forceinline__ void cp16(uint32_t dst, const void* src) {
    asm volatile("cp.async.cg.shared.global [%0], [%1], 16;"
                 :: "r"(dst), "l"(src) : "memory");
}
#define CP_COMMIT() asm volatile("cp.async.commit_group;" ::: "memory")
#define CP_WAIT0()  asm volatile("cp.async.wait_group 0;" ::: "memory")

__device__ __forceinline__ void mma_tf32(float& c0, float& c1, float& c2, float& c3,
                                         uint32_t a0, uint32_t a1, uint32_t a2, uint32_t a3,
                                         uint32_t b0, uint32_t b1) {
    asm volatile(
        "mma.sync.aligned.m16n8k8.row.col.f32.tf32.tf32.f32 "
        "{%0,%1,%2,%3}, {%4,%5,%6,%7}, {%8,%9}, {%0,%1,%2,%3};"
        : "+f"(c0), "+f"(c1), "+f"(c2), "+f"(c3)
        : "r"(a0), "r"(a1), "r"(a2), "r"(a3), "r"(b0), "r"(b1));
}

// ============================================================================
// Kernel 0: K/V fp32 -> tf32 pre-conversion, tile-ready layouts.
// pp(l) within 8-group: stored order (0,4,1,5,2,6,3,7) -> (t, t+4) adjacent,
// enabling LDS.64 fragment loads.                         [validated R10]
// K: word = kpos*128 + (pp(c) ^ ((kpos&3)<<3))            [validated R10]
// V: word = kpos*128 + (c ^ ((kpos&3)<<3))                [validated R11]
// grid (512, 2), 256 threads; 8192 words per block.
// ============================================================================
__global__ void __launch_bounds__(256)
cvt_kernel(const float* __restrict__ Kg, const float* __restrict__ Vg) {
    const int tid = threadIdx.x;
    const size_t base = (size_t)blockIdx.x * 8192;
    if (blockIdx.y == 1) {
        #pragma unroll
        for (int i = 0; i < 8; i++) {
            uint32_t w = (tid + i * 256) * 4;               // dest word offset
            uint32_t r = (w >> 7) & 3;                      // kpos & 3
            uint32_t dcol = w & 127;
            uint32_t gL = (((dcol >> 3) ^ r) << 3);         // logical 8-col group
            const float* src = Kg + base + (w & ~127u) + gL;
            uint4 o;
            if (((dcol >> 2) & 1) == 0) {
                o.x = f2tf32(src[0]); o.y = f2tf32(src[4]);
                o.z = f2tf32(src[1]); o.w = f2tf32(src[5]);
            } else {
                o.x = f2tf32(src[2]); o.y = f2tf32(src[6]);
                o.z = f2tf32(src[3]); o.w = f2tf32(src[7]);
            }
            *(uint4*)(g_K + base + w) = o;
        }
    } else {
        #pragma unroll
        for (int i = 0; i < 8; i++) {
            uint32_t w = (tid + i * 256) * 4;
            uint32_t r3 = (w >> 7) & 3;                     // kpos & 3
            uint32_t c = w & 127;
            const float* src = Vg + base + (w & ~127u) + (c ^ (r3 << 3));
            float4 v = *(const float4*)src;
            uint4 o;
            o.x = f2tf32(v.x); o.y = f2tf32(v.y); o.z = f2tf32(v.z); o.w = f2tf32(v.w);
            *(uint4*)(g_V + base + w) = o;
        }
    }
}

// ============================================================================
// Kernel A: flash attention. grid = (SQ/128, BB), 256 threads (8 warps).
// Warp owns 16 q-rows; 32 k-tiles of 64 kpos, cp.async double-buffered
// linearly from pre-converted scratch. QK fragments via LDS.64 (pp layout).
// Writes UNNORMALIZED exp(scores) to attn, out = (E@V)/rowsum, inv -> g_inv.
// ============================================================================
__global__ void __launch_bounds__(256, 1)
attn_kernel(const float* __restrict__ Qg, const void* __restrict__ maskg,
            float* __restrict__ outg, float* __restrict__ attng, int has_attn) {
    extern __shared__ char smem[];
    const uint32_t sb = smem_u32(smem);
    uint32_t* const Qs = (uint32_t*)(smem + OFF_Q);

    const int tid = threadIdx.x, wid = tid >> 5, lane = tid & 31;
    const int g = lane >> 2, t = lane & 3;          // mma groupID / threadID
    const int qt = blockIdx.x, b = blockIdx.y;

    // ---- inline mask dtype detection (bool/uint8 vs int32) ----
    int bad = 0;
    { uint32_t w = ((const uint32_t*)maskg)[tid]; if (w & 0xffffff00u) bad = 1; }
    const int m32 = __syncthreads_or(bad) ? 0 : 1;

    const size_t mask_row0 = (size_t)(b * SQ + qt * 128);

    // ---- cp.async prefetch of tile kt into parity p (pure linear copies) ----
    auto issue_prefetch = [&](int kt, int p) {
        const size_t tbase = ((size_t)b * 32 + kt) * 8192;   // words
        const char* ksrc = (const char*)(g_K + tbase);
        const char* vsrc = (const char*)(g_V + tbase);
        const uint32_t kb = sb + OFF_K + p * 32768;
        const uint32_t vb = sb + OFF_V + p * 32768;
        #pragma unroll
        for (int j = 0; j < 8; j++) {
            int ci = tid + j * 256;                  // 2048 16B-chunks per tensor
            cp16(kb + ci * 16, ksrc + ci * 16);
            cp16(vb + ci * 16, vsrc + ci * 16);
        }
        if (!m32) {
            const uint8_t* msrc = (const uint8_t*)maskg + mask_row0 * SQ + (size_t)kt * 64;
            const uint32_t mb = sb + OFF_M + p * 10240;
            #pragma unroll
            for (int j = 0; j < 2; j++) {
                int ci = tid + j * 256;              // 512 chunks: 128 rows x 4
                int r = ci >> 2, q = ci & 3;
                cp16(mb + r * M_PITCH + q * 16, msrc + (size_t)r * SQ + q * 16);
            }
        }
        CP_COMMIT();
    };
    issue_prefetch(0, 0);

    // ---- stage Q once (fp32 -> tf32, pair-permuted + swizzled) ----
    {
        const float* qsrc = Qg + ((size_t)(b * SQ + qt * 128)) * DD;
        #pragma unroll
        for (int i = 0; i < 16; i++) {
            int idx = tid + i * 256;
            int r = idx >> 5, f = idx & 31;
            float4 v = ((const float4*)(qsrc + (size_t)r * DD))[f];
            uint32_t xr = (r & 3) << 3;
            #pragma unroll
            for (int j = 0; j < 4; j++) {
                int c = 4 * f + j;
                uint32_t pp = (c & ~7) | ((c & 3) << 1) | ((c >> 2) & 1);
                Qs[r * 128 + (pp ^ xr)] = f2tf32(((const float*)&v)[j]);
            }
        }
    }

    // persistent accumulators: O tile (16 rows x 128 d per warp) + rowsums
    float o[16][4];
    #pragma unroll
    for (int nt = 0; nt < 16; nt++) { o[nt][0] = o[nt][1] = o[nt][2] = o[nt][3] = 0.0f; }
    float lsum0 = 0.0f, lsum1 = 0.0f;

    const int qrow_l = wid * 16 + g;                       // CTA-local query row
    const size_t qrow_g = (size_t)(b * SQ + qt * 128) + qrow_l;

    const int srcA = (lane & 0x1C) | ((lane & 3) >> 1);    // C->A frag shuffle srcs
    const int srcB = srcA + 2;
    const bool sel = lane & 1;
    const uint32_t xg = (uint32_t)(g & 3) << 3;

    for (int kt = 0; kt < 32; kt++) {
        const int p = kt & 1;
        uint32_t* const Ks = (uint32_t*)(smem + OFF_K + p * 32768);
        uint32_t* const Vs = (uint32_t*)(smem + OFF_V + p * 32768);
        uint8_t*  const Ms = (uint8_t*)(smem + OFF_M + p * 10240);

        CP_WAIT0();
        __syncthreads();   // tile kt landed; all warps done with buffer p^1

        // prefetch next tile into the other buffers (overlaps compute)
        if (kt < 31) issue_prefetch(kt + 1, p ^ 1);

        // ---- int32 mask fallback: manual stage (packed to bytes) ----
        if (m32) {
            const int* msrc = (const int*)maskg;
            #pragma unroll
            for (int i = 0; i < 8; i++) {
                int lin = tid + i * 256;               // 2048 groups of 4 ints
                int r = lin >> 4, gi = lin & 15;
                size_t off = (mask_row0 + r) * SQ + kt * 64 + 4 * gi;
                uint4 x = *(const uint4*)(msrc + off);
                uint32_t packed = (x.x & 0xffu) | ((x.y & 0xffu) << 8) |
                                  ((x.z & 0xffu) << 16) | ((x.w & 0xffu) << 24);
                *(uint32_t*)(Ms + r * M_PITCH + 4 * gi) = packed;
            }
            __syncthreads();
        }

        // ---- QK^T: scores C (16 rows x 64 kpos per warp), LDS.64 frags ----
        float c[8][4];
        #pragma unroll
        for (int nt = 0; nt < 8; nt++) { c[nt][0] = c[nt][1] = c[nt][2] = c[nt][3] = 0.0f; }

        #pragma unroll
        for (int ks = 0; ks < 16; ks++) {
            const uint32_t pc = ((uint32_t)(8 * ks + 2 * t)) ^ xg;
            const uint2 a01 = *(const uint2*)(Qs + qrow_l * 128 + pc);
            const uint2 a23 = *(const uint2*)(Qs + (qrow_l + 8) * 128 + pc);
            #pragma unroll
            for (int nt = 0; nt < 8; nt++) {
                const uint2 bb = *(const uint2*)(Ks + (8 * nt + g) * 128 + pc);
                mma_tf32(c[nt][0], c[nt][1], c[nt][2], c[nt][3],
                         a01.x, a23.x, a01.y, a23.y, bb.x, bb.y);
            }
        }

        // ---- softmax numerator: mask, exp, rowsum, attn write ----
        float* arow0 = attng + qrow_g * SQ + kt * 64;
        float* arow1 = arow0 + 8 * (size_t)SQ;
        const uint8_t* mrow0 = Ms + qrow_l * M_PITCH;
        const uint8_t* mrow1 = Ms + (qrow_l + 8) * M_PITCH;
        #pragma unroll
        for (int nt = 0; nt < 8; nt++) {
            const int cb = 8 * nt + 2 * t;
            uint32_t m0 = *(const uint16_t*)(mrow0 + cb);
            uint32_t m1 = *(const uint16_t*)(mrow1 + cb);
            float e0 = (m0 & 0xffu) ? 0.0f : __expf(c[nt][0] * QK_SCALE);
            float e1 = (m0 >> 8)    ? 0.0f : __expf(c[nt][1] * QK_SCALE);
            float e2 = (m1 & 0xffu) ? 0.0f : __expf(c[nt][2] * QK_SCALE);
            float e3 = (m1 >> 8)    ? 0.0f : __expf(c[nt][3] * QK_SCALE);
            c[nt][0] = e0; c[nt][1] = e1; c[nt][2] = e2; c[nt][3] = e3;
            lsum0 += e0 + e1;
            lsum1 += e2 + e3;
            if (has_attn) {
                __stcs((float2*)(arow0 + cb), make_float2(e0, e1));
                __stcs((float2*)(arow1 + cb), make_float2(e2, e3));
            }
        }

        // ---- PV: O += E @ V. C-frag(ks2) -> A-frag via shuffles. ----
        #pragma unroll
        for (int ks2 = 0; ks2 < 8; ks2++) {
            float v00 = __shfl_sync(0xffffffffu, c[ks2][0], srcA);
            float v01 = __shfl_sync(0xffffffffu, c[ks2][1], srcA);
            float v20 = __shfl_sync(0xffffffffu, c[ks2][2], srcA);
            float v21 = __shfl_sync(0xffffffffu, c[ks2][3], srcA);
            float w00 = __shfl_sync(0xffffffffu, c[ks2][0], srcB);
            float w01 = __shfl_sync(0xffffffffu, c[ks2][1], srcB);
            float w20 = __shfl_sync(0xffffffffu, c[ks2][2], srcB);
            float w21 = __shfl_sync(0xffffffffu, c[ks2][3], srcB);
            const uint32_t a0 = f2tf32(sel ? v01 : v00);
            const uint32_t a1 = f2tf32(sel ? v21 : v20);
            const uint32_t a2 = f2tf32(sel ? w01 : w00);
            const uint32_t a3 = f2tf32(sel ? w21 : w20);
            const int vr0 = 8 * ks2 + t;
            const int vr4 = vr0 + 4;
            #pragma unroll
            for (int nt = 0; nt < 16; nt++) {
                const int cc = (8 * nt + g) ^ (t << 3);
                const uint32_t b0 = Vs[vr0 * 128 + cc];
                const uint32_t b1 = Vs[vr4 * 128 + cc];
                mma_tf32(o[nt][0], o[nt][1], o[nt][2], o[nt][3],
                         a0, a1, a2, a3, b0, b1);
            }
        }
    }

    // ---- reduce rowsums across the quad ----
    lsum0 += __shfl_xor_sync(0xffffffffu, lsum0, 1);
    lsum0 += __shfl_xor_sync(0xffffffffu, lsum0, 2);
    lsum1 += __shfl_xor_sync(0xffffffffu, lsum1, 1);
    lsum1 += __shfl_xor_sync(0xffffffffu, lsum1, 2);
    const float inv0 = 1.0f / lsum0;
    const float inv1 = 1.0f / lsum1;
    if (t == 0) {
        g_inv[qrow_g]     = inv0;
        g_inv[qrow_g + 8] = inv1;
    }

    // ---- out = O / rowsum ----
    float* orow0 = outg + qrow_g * DD;
    float* orow1 = orow0 + 8 * (size_t)DD;
    #pragma unroll
    for (int nt = 0; nt < 16; nt++) {
        const int cb = 8 * nt + 2 * t;
        *(float2*)(orow0 + cb) = make_float2(o[nt][0] * inv0, o[nt][1] * inv0);
        *(float2*)(orow1 + cb) = make_float2(o[nt][2] * inv1, o[nt][3] * inv1);
    }
}

// ============================================================================
// Kernel B: attn[i] *= 1/rowsum (float4 grid-stride) — measured 75us @80% DRAM
// ============================================================================
__global__ void __launch_bounds__(256)
norm_kernel(float* __restrict__ attn) {
    const size_t n4 = (size_t)BB * SQ * SQ / 4;       // 16,777,216 float4
    const size_t stride = (size_t)gridDim.x * 256;
    for (size_t i = (size_t)blockIdx.x * 256 + threadIdx.x; i < n4; i += stride) {
        float inv = g_inv[i >> 9];                     // 512 float4 per row
        float4 v = ((const float4*)attn)[i];
        v.x *= inv; v.y *= inv; v.z *= inv; v.w *= inv;
        ((float4*)attn)[i] = v;
    }
}

// ============================================================================
// Launch
// ============================================================================
extern "C" void kernel_launch(void* const* d_in, const int* in_sizes, int n_in,
                              void* d_out, int out_size) {
    const float* Q = (const float*)d_in[0];
    const float* K = (const float*)d_in[1];
    const float* V = (const float*)d_in[2];
    const void*  M = d_in[3];

    float* out = (float*)d_out;
    const long long out_elems  = (long long)BB * SQ * DD;              // 4,194,304
    const long long attn_elems = (long long)BB * SQ * SQ;              // 67,108,864
    int has_attn = ((long long)out_size >= out_elems + attn_elems) ? 1 : 0;
    float* attn = has_attn ? (out + out_elems) : out;   // dummy ptr if unused

    cudaFuncSetAttribute(attn_kernel,
                         cudaFuncAttributeMaxDynamicSharedMemorySize, SMEM_TOTAL);

    cvt_kernel<<<dim3(512, 2), 256>>>(K, V);
    attn_kernel<<<dim3(SQ / 128, BB), 256, SMEM_TOTAL>>>(Q, M, out, attn, has_attn);
    if (has_attn)
        norm_kernel<<<8192, 256>>>(attn);
}

// round 15
// speedup vs baseline: 1.4131x; 1.0039x over previous
#include <cuda_runtime.h>
#include <cstdint>
#include <cstddef>

// ============================================================================
// Problem constants
// ============================================================================
static constexpr int BB  = 16;
static constexpr int SQ  = 2048;
static constexpr int DD  = 128;
static constexpr float QK_SCALE = 0.08838834764831845f;  // 1/sqrt(128)

// SMEM layout (bytes), 1 CTA/SM, 256 threads:
// Q : 128 rows x 128 words, pair-permuted + swizzled (64 KB), staged once
// K : double-buffered 64 kpos x 128 d word tiles, pp + swizzle (32 KB each)
// Vt: double-buffered 128 d x 64 kpos word tiles, kpos-pp + swizzle (32 KB each)
// M : double-buffered mask tiles, 128 rows x 64 byte-cols, 80B pitch
static constexpr int OFF_Q  = 0;
static constexpr int OFF_K  = 65536;     // + p*32768
static constexpr int OFF_V  = 131072;    // + p*32768
static constexpr int OFF_M  = 196608;    // + p*10240
static constexpr int M_PITCH = 80;
static constexpr int SMEM_TOTAL = OFF_M + 2 * 10240;   // 217088 B

// ============================================================================
// Device globals (no dynamic allocation allowed)
// ============================================================================
__device__ float    g_inv[BB * SQ];
__device__ uint32_t g_K[(size_t)BB * SQ * DD];   // tf32 [kpos][d], pp + swizzle
__device__ uint32_t g_V[(size_t)BB * SQ * DD];   // tf32 per-tile [d][kpos], pp + swizzle

// ============================================================================
// Helpers
// ============================================================================
__device__ __forceinline__ uint32_t smem_u32(const void* p) {
    uint32_t a;
    asm("{ .reg .u64 t; cvta.to.shared.u64 t, %1; cvt.u32.u64 %0, t; }"
        : "=r"(a) : "l"(p));
    return a;
}

__device__ __forceinline__ uint32_t f2tf32(float f) {
    uint32_t r;
    asm("cvt.rna.tf32.f32 %0, %1;" : "=r"(r) : "f"(f));
    return r;
}

__device__ __forceinline__ void cp16(uint32_t dst, const void* src) {
    asm volatile("cp.async.cg.shared.global [%0], [%1], 16;"
                 :: "r"(dst), "l"(src) : "memory");
}
#define CP_COMMIT() asm volatile("cp.async.commit_group;" ::: "memory")
#define CP_WAIT0()  asm volatile("cp.async.wait_group 0;" ::: "memory")

__device__ __forceinline__ void mma_tf32(float& c0, float& c1, float& c2, float& c3,
                                         uint32_t a0, uint32_t a1, uint32_t a2, uint32_t a3,
                                         uint32_t b0, uint32_t b1) {
    asm volatile(
        "mma.sync.aligned.m16n8k8.row.col.f32.tf32.tf32.f32 "
        "{%0,%1,%2,%3}, {%4,%5,%6,%7}, {%8,%9}, {%0,%1,%2,%3};"
        : "+f"(c0), "+f"(c1), "+f"(c2), "+f"(c3)
        : "r"(a0), "r"(a1), "r"(a2), "r"(a3), "r"(b0), "r"(b1));
}

// ============================================================================
// Kernel 0: K/V fp32 -> tf32 pre-conversion, tile-ready layouts.
// pp within 8-group: stored order (0,4,1,5,2,6,3,7) -> (t, t+4) adjacent,
// enabling LDS.64 fragment loads.
// K: word = kpos*128 + (pp(c) ^ ((kpos&3)<<3))              [validated R10/R13]
// Vt: per 64-kpos tile: word = d*64 + (pp(kp) ^ ((d&3)<<3)) [R7 layout;
//     bit-identical outputs to validated layout under shared-loop test]
// grid (512, 2), 256 threads; 8192 words per block.
// ============================================================================
__global__ void __launch_bounds__(256)
cvt_kernel(const float* __restrict__ Kg, const float* __restrict__ Vg) {
    const int tid = threadIdx.x;
    const size_t base = (size_t)blockIdx.x * 8192;
    if (blockIdx.y == 1) {
        #pragma unroll
        for (int i = 0; i < 8; i++) {
            uint32_t w = (tid + i * 256) * 4;               // dest word offset
            uint32_t r = (w >> 7) & 3;                      // kpos & 3
            uint32_t dcol = w & 127;
            uint32_t gL = (((dcol >> 3) ^ r) << 3);         // logical 8-col group
            const float* src = Kg + base + (w & ~127u) + gL;
            uint4 o;
            if (((dcol >> 2) & 1) == 0) {
                o.x = f2tf32(src[0]); o.y = f2tf32(src[4]);
                o.z = f2tf32(src[1]); o.w = f2tf32(src[5]);
            } else {
                o.x = f2tf32(src[2]); o.y = f2tf32(src[6]);
                o.z = f2tf32(src[3]); o.w = f2tf32(src[7]);
            }
            *(uint4*)(g_K + base + w) = o;
        }
    } else {
        __shared__ uint32_t s[64 * 129];                    // [kp][d], pitch 129
        #pragma unroll
        for (int i = 0; i < 8; i++) {
            int i4 = tid + i * 256;                         // 2048 float4
            int kp = i4 >> 5, d4 = i4 & 31;
            float4 v = ((const float4*)(Vg + base))[i4];
            uint32_t* ps = s + kp * 129 + d4 * 4;
            ps[0] = f2tf32(v.x); ps[1] = f2tf32(v.y);
            ps[2] = f2tf32(v.z); ps[3] = f2tf32(v.w);
        }
        __syncthreads();
        #pragma unroll
        for (int i = 0; i < 32; i++) {
            int w = tid + i * 256;                          // 0..8191
            int d = w >> 6, colout = w & 63;
            int ppk = colout ^ ((d & 3) << 3);
            int kp = (ppk & ~7) | ((ppk & 7) >> 1) | ((ppk & 1) << 2);
            g_V[base + w] = s[kp * 129 + d];
        }
    }
}

// ============================================================================
// Kernel A: flash attention. grid = (SQ/128, BB), 256 threads (8 warps).
// Warp owns 16 q-rows; 32 k-tiles of 64 kpos, cp.async double-buffered
// linearly from pre-converted scratch. QK AND PV fragments via LDS.64.
// Writes UNNORMALIZED exp(scores) to attn, out = (E@V)/rowsum, inv -> g_inv.
// ============================================================================
__global__ void __launch_bounds__(256, 1)
attn_kernel(const float* __restrict__ Qg, const void* __restrict__ maskg,
            float* __restrict__ outg, float* __restrict__ attng, int has_attn) {
    extern __shared__ char smem[];
    const uint32_t sb = smem_u32(smem);
    uint32_t* const Qs = (uint32_t*)(smem + OFF_Q);

    const int tid = threadIdx.x, wid = tid >> 5, lane = tid & 31;
    const int g = lane >> 2, t = lane & 3;          // mma groupID / threadID
    const int qt = blockIdx.x, b = blockIdx.y;

    // ---- inline mask dtype detection (bool/uint8 vs int32) ----
    int bad = 0;
    { uint32_t w = ((const uint32_t*)maskg)[tid]; if (w & 0xffffff00u) bad = 1; }
    const int m32 = __syncthreads_or(bad) ? 0 : 1;

    const size_t mask_row0 = (size_t)(b * SQ + qt * 128);

    // ---- cp.async prefetch of tile kt into parity p (pure linear copies) ----
    auto issue_prefetch = [&](int kt, int p) {
        const size_t tbase = ((size_t)b * 32 + kt) * 8192;   // words
        const char* ksrc = (const char*)(g_K + tbase);
        const char* vsrc = (const char*)(g_V + tbase);
        const uint32_t kb = sb + OFF_K + p * 32768;
        const uint32_t vb = sb + OFF_V + p * 32768;
        #pragma unroll
        for (int j = 0; j < 8; j++) {
            int ci = tid + j * 256;                  // 2048 16B-chunks per tensor
            cp16(kb + ci * 16, ksrc + ci * 16);
            cp16(vb + ci * 16, vsrc + ci * 16);
        }
        if (!m32) {
            const uint8_t* msrc = (const uint8_t*)maskg + mask_row0 * SQ + (size_t)kt * 64;
            const uint32_t mb = sb + OFF_M + p * 10240;
            #pragma unroll
            for (int j = 0; j < 2; j++) {
                int ci = tid + j * 256;              // 512 chunks: 128 rows x 4
                int r = ci >> 2, q = ci & 3;
                cp16(mb + r * M_PITCH + q * 16, msrc + (size_t)r * SQ + q * 16);
            }
        }
        CP_COMMIT();
    };
    issue_prefetch(0, 0);

    // ---- stage Q once (fp32 -> tf32, pair-permuted + swizzled) ----
    {
        const float* qsrc = Qg + ((size_t)(b * SQ + qt * 128)) * DD;
        #pragma unroll
        for (int i = 0; i < 16; i++) {
            int idx = tid + i * 256;
            int r = idx >> 5, f = idx & 31;
            float4 v = ((const float4*)(qsrc + (size_t)r * DD))[f];
            uint32_t xr = (r & 3) << 3;
            #pragma unroll
            for (int j = 0; j < 4; j++) {
                int c = 4 * f + j;
                uint32_t pp = (c & ~7) | ((c & 3) << 1) | ((c >> 2) & 1);
                Qs[r * 128 + (pp ^ xr)] = f2tf32(((const float*)&v)[j]);
            }
        }
    }

    // persistent accumulators: O tile (16 rows x 128 d per warp) + rowsums
    float o[16][4];
    #pragma unroll
    for (int nt = 0; nt < 16; nt++) { o[nt][0] = o[nt][1] = o[nt][2] = o[nt][3] = 0.0f; }
    float lsum0 = 0.0f, lsum1 = 0.0f;

    const int qrow_l = wid * 16 + g;                       // CTA-local query row
    const size_t qrow_g = (size_t)(b * SQ + qt * 128) + qrow_l;

    const int srcA = (lane & 0x1C) | ((lane & 3) >> 1);    // C->A frag shuffle srcs
    const int srcB = srcA + 2;
    const bool sel = lane & 1;
    const uint32_t xg = (uint32_t)(g & 3) << 3;

    for (int kt = 0; kt < 32; kt++) {
        const int p = kt & 1;
        uint32_t* const Ks = (uint32_t*)(smem + OFF_K + p * 32768);
        uint32_t* const Vt = (uint32_t*)(smem + OFF_V + p * 32768);
        uint8_t*  const Ms = (uint8_t*)(smem + OFF_M + p * 10240);

        CP_WAIT0();
        __syncthreads();   // tile kt landed; all warps done with buffer p^1

        // prefetch next tile into the other buffers (overlaps compute)
        if (kt < 31) issue_prefetch(kt + 1, p ^ 1);

        // ---- int32 mask fallback: manual stage (packed to bytes) ----
        if (m32) {
            const int* msrc = (const int*)maskg;
            #pragma unroll
            for (int i = 0; i < 8; i++) {
                int lin = tid + i * 256;               // 2048 groups of 4 ints
                int r = lin >> 4, gi = lin & 15;
                size_t off = (mask_row0 + r) * SQ + kt * 64 + 4 * gi;
                uint4 x = *(const uint4*)(msrc + off);
                uint32_t packed = (x.x & 0xffu) | ((x.y & 0xffu) << 8) |
                                  ((x.z & 0xffu) << 16) | ((x.w & 0xffu) << 24);
                *(uint32_t*)(Ms + r * M_PITCH + 4 * gi) = packed;
            }
            __syncthreads();
        }

        // ---- QK^T: scores C (16 rows x 64 kpos per warp), LDS.64 frags ----
        float c[8][4];
        #pragma unroll
        for (int nt = 0; nt < 8; nt++) { c[nt][0] = c[nt][1] = c[nt][2] = c[nt][3] = 0.0f; }

        #pragma unroll
        for (int ks = 0; ks < 16; ks++) {
            const uint32_t pc = ((uint32_t)(8 * ks + 2 * t)) ^ xg;
            const uint2 a01 = *(const uint2*)(Qs + qrow_l * 128 + pc);
            const uint2 a23 = *(const uint2*)(Qs + (qrow_l + 8) * 128 + pc);
            #pragma unroll
            for (int nt = 0; nt < 8; nt++) {
                const uint2 bb = *(const uint2*)(Ks + (8 * nt + g) * 128 + pc);
                mma_tf32(c[nt][0], c[nt][1], c[nt][2], c[nt][3],
                         a01.x, a23.x, a01.y, a23.y, bb.x, bb.y);
            }
        }

        // ---- softmax numerator: mask, exp, rowsum, attn write ----
        float* arow0 = attng + qrow_g * SQ + kt * 64;
        float* arow1 = arow0 + 8 * (size_t)SQ;
        const uint8_t* mrow0 = Ms + qrow_l * M_PITCH;
        const uint8_t* mrow1 = Ms + (qrow_l + 8) * M_PITCH;
        #pragma unroll
        for (int nt = 0; nt < 8; nt++) {
            const int cb = 8 * nt + 2 * t;
            uint32_t m0 = *(const uint16_t*)(mrow0 + cb);
            uint32_t m1 = *(const uint16_t*)(mrow1 + cb);
            float e0 = (m0 & 0xffu) ? 0.0f : __expf(c[nt][0] * QK_SCALE);
            float e1 = (m0 >> 8)    ? 0.0f : __expf(c[nt][1] * QK_SCALE);
            float e2 = (m1 & 0xffu) ? 0.0f : __expf(c[nt][2] * QK_SCALE);
            float e3 = (m1 >> 8)    ? 0.0f : __expf(c[nt][3] * QK_SCALE);
            c[nt][0] = e0; c[nt][1] = e1; c[nt][2] = e2; c[nt][3] = e3;
            lsum0 += e0 + e1;
            lsum1 += e2 + e3;
            if (has_attn) {
                __stcs((float2*)(arow0 + cb), make_float2(e0, e1));
                __stcs((float2*)(arow1 + cb), make_float2(e2, e3));
            }
        }

        // ---- PV: O += E @ V. C-frag(ks2) -> A-frag via shuffles; B = LDS.64
        //      from transposed, kpos-pair-permuted V tile. ----
        #pragma unroll
        for (int ks2 = 0; ks2 < 8; ks2++) {
            float v00 = __shfl_sync(0xffffffffu, c[ks2][0], srcA);
            float v01 = __shfl_sync(0xffffffffu, c[ks2][1], srcA);
            float v20 = __shfl_sync(0xffffffffu, c[ks2][2], srcA);
            float v21 = __shfl_sync(0xffffffffu, c[ks2][3], srcA);
            float w00 = __shfl_sync(0xffffffffu, c[ks2][0], srcB);
            float w01 = __shfl_sync(0xffffffffu, c[ks2][1], srcB);
            float w20 = __shfl_sync(0xffffffffu, c[ks2][2], srcB);
            float w21 = __shfl_sync(0xffffffffu, c[ks2][3], srcB);
            const uint32_t a0 = f2tf32(sel ? v01 : v00);
            const uint32_t a1 = f2tf32(sel ? v21 : v20);
            const uint32_t a2 = f2tf32(sel ? w01 : w00);
            const uint32_t a3 = f2tf32(sel ? w21 : w20);
            const uint32_t pk = ((uint32_t)(8 * ks2 + 2 * t)) ^ xg;
            #pragma unroll
            for (int nt = 0; nt < 16; nt++) {
                const uint2 bb = *(const uint2*)(Vt + (8 * nt + g) * 64 + pk);
                mma_tf32(o[nt][0], o[nt][1], o[nt][2], o[nt][3],
                         a0, a1, a2, a3, bb.x, bb.y);
            }
        }
    }

    // ---- reduce rowsums across the quad ----
    lsum0 += __shfl_xor_sync(0xffffffffu, lsum0, 1);
    lsum0 += __shfl_xor_sync(0xffffffffu, lsum0, 2);
    lsum1 += __shfl_xor_sync(0xffffffffu, lsum1, 1);
    lsum1 += __shfl_xor_sync(0xffffffffu, lsum1, 2);
    const float inv0 = 1.0f / lsum0;
    const float inv1 = 1.0f / lsum1;
    if (t == 0) {
        g_inv[qrow_g]     = inv0;
        g_inv[qrow_g + 8] = inv1;
    }

    // ---- out = O / rowsum ----
    float* orow0 = outg + qrow_g * DD;
    float* orow1 = orow0 + 8 * (size_t)DD;
    #pragma unroll
    for (int nt = 0; nt < 16; nt++) {
        const int cb = 8 * nt + 2 * t;
        *(float2*)(orow0 + cb) = make_float2(o[nt][0] * inv0, o[nt][1] * inv0);
        *(float2*)(orow1 + cb) = make_float2(o[nt][2] * inv1, o[nt][3] * inv1);
    }
}

// ============================================================================
// Kernel B: attn[i] *= 1/rowsum (float4 grid-stride) — measured 75us @80% DRAM
// ============================================================================
__global__ void __launch_bounds__(256)
norm_kernel(float* __restrict__ attn) {
    const size_t n4 = (size_t)BB * SQ * SQ / 4;       // 16,777,216 float4
    const size_t stride = (size_t)gridDim.x * 256;
    for (size_t i = (size_t)blockIdx.x * 256 + threadIdx.x; i < n4; i += stride) {
        float inv = g_inv[i >> 9];                     // 512 float4 per row
        float4 v = ((const float4*)attn)[i];
        v.x *= inv; v.y *= inv; v.z *= inv; v.w *= inv;
        ((float4*)attn)[i] = v;
    }
}

// ============================================================================
// Launch
// ============================================================================
extern "C" void kernel_launch(void* const* d_in, const int* in_sizes, int n_in,
                              void* d_out, int out_size) {
    const float* Q = (const float*)d_in[0];
    const float* K = (const float*)d_in[1];
    const float* V = (const float*)d_in[2];
    const void*  M = d_in[3];

    float* out = (float*)d_out;
    const long long out_elems  = (long long)BB * SQ * DD;              // 4,194,304
    const long long attn_elems = (long long)BB * SQ * SQ;              // 67,108,864
    int has_attn = ((long long)out_size >= out_elems + attn_elems) ? 1 : 0;
    float* attn = has_attn ? (out + out_elems) : out;   // dummy ptr if unused

    cudaFuncSetAttribute(attn_kernel,
                         cudaFuncAttributeMaxDynamicSharedMemorySize, SMEM_TOTAL);

    cvt_kernel<<<dim3(512, 2), 256>>>(K, V);
    attn_kernel<<<dim3(SQ / 128, BB), 256, SMEM_TOTAL>>>(Q, M, out, attn, has_attn);
    if (has_attn)
        norm_kernel<<<8192, 256>>>(attn);
}

// round 16
// speedup vs baseline: 1.5769x; 1.1159x over previous
#include <cuda_runtime.h>
#include <cstdint>
#include <cstddef>

// ============================================================================
// Problem constants
// ============================================================================
static constexpr int BB  = 16;
static constexpr int SQ  = 2048;
static constexpr int DD  = 128;
static constexpr float QK_SCALE = 0.08838834764831845f;  // 1/sqrt(128)

// Kernel A SMEM (bytes), 2 CTAs/SM, 256 threads:
// Q : 128 rows x 128 words, pair-permuted + swizzled (64 KB), staged once
// K : double-buffered 32 kpos x 128 d word tiles, pp + swizzle (16 KB each)
// M : double-buffered mask tiles, 128 rows x 32 byte-cols, 48B pitch (6 KB)
static constexpr int A_OFF_Q = 0;
static constexpr int A_OFF_K = 65536;    // + p*16384
static constexpr int A_OFF_M = 98304;    // + p*6144
static constexpr int A_SMEM  = 110592;

// Kernel C SMEM (bytes), 2 CTAs/SM, 256 threads:
// E : double-buffered 128 q x 32 kpos fp32, pitch 36 words (18 KB each)
// V : double-buffered 128 d x 32 kpos tf32 half-tiles (16 KB each)
static constexpr int C_OFF_E = 0;        // + p*18432
static constexpr int C_OFF_V = 36864;    // + p*16384
static constexpr int C_SMEM  = 69632;

// ============================================================================
// Device globals (no dynamic allocation allowed)
// ============================================================================
__device__ float    g_inv[BB * SQ];
__device__ uint32_t g_K[(size_t)BB * SQ * DD];   // tf32 [kpos][d], pp + swizzle
__device__ uint32_t g_V[(size_t)BB * SQ * DD];   // tf32 per-64-tile [d][kpos], pp + swizzle
__device__ float    g_E[(size_t)BB * SQ * SQ];   // fallback E when attn not in output

// ============================================================================
// Helpers
// ============================================================================
__device__ __forceinline__ uint32_t smem_u32(const void* p) {
    uint32_t a;
    asm("{ .reg .u64 t; cvta.to.shared.u64 t, %1; cvt.u32.u64 %0, t; }"
        : "=r"(a) : "l"(p));
    return a;
}

__device__ __forceinline__ uint32_t f2tf32(float f) {
    uint32_t r;
    asm("cvt.rna.tf32.f32 %0, %1;" : "=r"(r) : "f"(f));
    return r;
}

__device__ __forceinline__ void cp16(uint32_t dst, const void* src) {
    asm volatile("cp.async.cg.shared.global [%0], [%1], 16;"
                 :: "r"(dst), "l"(src) : "memory");
}
#define CP_COMMIT() asm volatile("cp.async.commit_group;" ::: "memory")
#define CP_WAIT0()  asm volatile("cp.async.wait_group 0;" ::: "memory")

__device__ __forceinline__ void mma_tf32(float& c0, float& c1, float& c2, float& c3,
                                         uint32_t a0, uint32_t a1, uint32_t a2, uint32_t a3,
                                         uint32_t b0, uint32_t b1) {
    asm volatile(
        "mma.sync.aligned.m16n8k8.row.col.f32.tf32.tf32.f32 "
        "{%0,%1,%2,%3}, {%4,%5,%6,%7}, {%8,%9}, {%0,%1,%2,%3};"
        : "+f"(c0), "+f"(c1), "+f"(c2), "+f"(c3)
        : "r"(a0), "r"(a1), "r"(a2), "r"(a3), "r"(b0), "r"(b1));
}

// ============================================================================
// Kernel 0: K/V fp32 -> tf32 pre-conversion (validated R13/R14 layouts).
// K: word = kpos*128 + (pp(c) ^ ((kpos&3)<<3)), pp: (0,4,1,5,2,6,3,7)
// Vt: per 64-kpos tile: word = d*64 + (pp(kp) ^ ((d&3)<<3))
// ============================================================================
__global__ void __launch_bounds__(256)
cvt_kernel(const float* __restrict__ Kg, const float* __restrict__ Vg) {
    const int tid = threadIdx.x;
    const size_t base = (size_t)blockIdx.x * 8192;
    if (blockIdx.y == 1) {
        #pragma unroll
        for (int i = 0; i < 8; i++) {
            uint32_t w = (tid + i * 256) * 4;               // dest word offset
            uint32_t r = (w >> 7) & 3;                      // kpos & 3
            uint32_t dcol = w & 127;
            uint32_t gL = (((dcol >> 3) ^ r) << 3);         // logical 8-col group
            const float* src = Kg + base + (w & ~127u) + gL;
            uint4 o;
            if (((dcol >> 2) & 1) == 0) {
                o.x = f2tf32(src[0]); o.y = f2tf32(src[4]);
                o.z = f2tf32(src[1]); o.w = f2tf32(src[5]);
            } else {
                o.x = f2tf32(src[2]); o.y = f2tf32(src[6]);
                o.z = f2tf32(src[3]); o.w = f2tf32(src[7]);
            }
            *(uint4*)(g_K + base + w) = o;
        }
    } else {
        __shared__ uint32_t s[64 * 129];                    // [kp][d], pitch 129
        #pragma unroll
        for (int i = 0; i < 8; i++) {
            int i4 = tid + i * 256;                         // 2048 float4
            int kp = i4 >> 5, d4 = i4 & 31;
            float4 v = ((const float4*)(Vg + base))[i4];
            uint32_t* ps = s + kp * 129 + d4 * 4;
            ps[0] = f2tf32(v.x); ps[1] = f2tf32(v.y);
            ps[2] = f2tf32(v.z); ps[3] = f2tf32(v.w);
        }
        __syncthreads();
        #pragma unroll
        for (int i = 0; i < 32; i++) {
            int w = tid + i * 256;                          // 0..8191
            int d = w >> 6, colout = w & 63;
            int ppk = colout ^ ((d & 3) << 3);
            int kp = (ppk & ~7) | ((ppk & 7) >> 1) | ((ppk & 1) << 2);
            g_V[base + w] = s[kp * 129 + d];
        }
    }
}

// ============================================================================
// Kernel A: QK^T + softmax numerator. grid (16,16), 256 thr, 2 CTAs/SM,
// single wave. 64 k-tiles of 32 kpos, cp.async double-buffered.
// Writes UNNORMALIZED exp(scores) to Eg and 1/rowsum to g_inv.
// ============================================================================
__global__ void __launch_bounds__(256, 2)
qk_kernel(const float* __restrict__ Qg, const void* __restrict__ maskg,
          float* __restrict__ Eg) {
    extern __shared__ char smem[];
    const uint32_t sb = smem_u32(smem);
    uint32_t* const Qs = (uint32_t*)(smem + A_OFF_Q);

    const int tid = threadIdx.x, wid = tid >> 5, lane = tid & 31;
    const int g = lane >> 2, t = lane & 3;
    const int qt = blockIdx.x, b = blockIdx.y;

    // ---- inline mask dtype detection (bool/uint8 vs int32) ----
    int bad = 0;
    { uint32_t w = ((const uint32_t*)maskg)[tid]; if (w & 0xffffff00u) bad = 1; }
    const int m32 = __syncthreads_or(bad) ? 0 : 1;

    const size_t mask_row0 = (size_t)(b * SQ + qt * 128);

    auto issue_prefetch = [&](int kt, int p) {
        const char* ksrc = (const char*)(g_K + (size_t)b * (SQ * DD) + kt * 4096);
        const uint32_t kb = sb + A_OFF_K + p * 16384;
        #pragma unroll
        for (int j = 0; j < 4; j++) {
            int ci = tid + j * 256;                  // 1024 16B-chunks
            cp16(kb + ci * 16, ksrc + ci * 16);
        }
        if (!m32) {
            const uint8_t* msrc = (const uint8_t*)maskg + mask_row0 * SQ + (size_t)kt * 32;
            const uint32_t mb = sb + A_OFF_M + p * 6144;
            int r = tid >> 1, h = tid & 1;           // 128 rows x 2 chunks
            cp16(mb + r * 48 + h * 16, msrc + (size_t)r * SQ + h * 16);
        }
        CP_COMMIT();
    };
    issue_prefetch(0, 0);

    // ---- stage Q once (fp32 -> tf32, pair-permuted + swizzled) ----
    {
        const float* qsrc = Qg + ((size_t)(b * SQ + qt * 128)) * DD;
        #pragma unroll
        for (int i = 0; i < 16; i++) {
            int idx = tid + i * 256;
            int r = idx >> 5, f = idx & 31;
            float4 v = ((const float4*)(qsrc + (size_t)r * DD))[f];
            uint32_t xr = (r & 3) << 3;
            #pragma unroll
            for (int j = 0; j < 4; j++) {
                int c = 4 * f + j;
                uint32_t pp = (c & ~7) | ((c & 3) << 1) | ((c >> 2) & 1);
                Qs[r * 128 + (pp ^ xr)] = f2tf32(((const float*)&v)[j]);
            }
        }
    }

    float lsum0 = 0.0f, lsum1 = 0.0f;
    const int qrow_l = wid * 16 + g;
    const size_t qrow_g = (size_t)(b * SQ + qt * 128) + qrow_l;
    const uint32_t xg = (uint32_t)(g & 3) << 3;

    for (int kt = 0; kt < 64; kt++) {
        const int p = kt & 1;
        uint32_t* const Ks = (uint32_t*)(smem + A_OFF_K + p * 16384);
        uint8_t*  const Ms = (uint8_t*)(smem + A_OFF_M + p * 6144);

        CP_WAIT0();
        __syncthreads();
        if (kt < 63) issue_prefetch(kt + 1, p ^ 1);

        if (m32) {
            const int* msrc = (const int*)maskg;
            #pragma unroll
            for (int i = 0; i < 4; i++) {
                int lin = tid + i * 256;               // 1024 groups of 4 ints
                int r = lin >> 3, gi = lin & 7;
                size_t off = (mask_row0 + r) * SQ + kt * 32 + 4 * gi;
                uint4 x = *(const uint4*)(msrc + off);
                uint32_t packed = (x.x & 0xffu) | ((x.y & 0xffu) << 8) |
                                  ((x.z & 0xffu) << 16) | ((x.w & 0xffu) << 24);
                *(uint32_t*)(Ms + r * 48 + 4 * gi) = packed;
            }
            __syncthreads();
        }

        // ---- QK^T: scores C (16 rows x 32 kpos per warp), LDS.64 frags ----
        float c[4][4];
        #pragma unroll
        for (int nt = 0; nt < 4; nt++) { c[nt][0] = c[nt][1] = c[nt][2] = c[nt][3] = 0.0f; }

        #pragma unroll
        for (int ks = 0; ks < 16; ks++) {
            const uint32_t pc = ((uint32_t)(8 * ks + 2 * t)) ^ xg;
            const uint2 a01 = *(const uint2*)(Qs + qrow_l * 128 + pc);
            const uint2 a23 = *(const uint2*)(Qs + (qrow_l + 8) * 128 + pc);
            #pragma unroll
            for (int nt = 0; nt < 4; nt++) {
                const uint2 bb = *(const uint2*)(Ks + (8 * nt + g) * 128 + pc);
                mma_tf32(c[nt][0], c[nt][1], c[nt][2], c[nt][3],
                         a01.x, a23.x, a01.y, a23.y, bb.x, bb.y);
            }
        }

        // ---- softmax numerator: mask, exp, rowsum, E write ----
        float* arow0 = Eg + qrow_g * SQ + kt * 32;
        float* arow1 = arow0 + 8 * (size_t)SQ;
        const uint8_t* mrow0 = Ms + qrow_l * 48;
        const uint8_t* mrow1 = Ms + (qrow_l + 8) * 48;
        #pragma unroll
        for (int nt = 0; nt < 4; nt++) {
            const int cb = 8 * nt + 2 * t;
            uint32_t m0 = *(const uint16_t*)(mrow0 + cb);
            uint32_t m1 = *(const uint16_t*)(mrow1 + cb);
            float e0 = (m0 & 0xffu) ? 0.0f : __expf(c[nt][0] * QK_SCALE);
            float e1 = (m0 >> 8)    ? 0.0f : __expf(c[nt][1] * QK_SCALE);
            float e2 = (m1 & 0xffu) ? 0.0f : __expf(c[nt][2] * QK_SCALE);
            float e3 = (m1 >> 8)    ? 0.0f : __expf(c[nt][3] * QK_SCALE);
            lsum0 += e0 + e1;
            lsum1 += e2 + e3;
            __stcs((float2*)(arow0 + cb), make_float2(e0, e1));
            __stcs((float2*)(arow1 + cb), make_float2(e2, e3));
        }
    }

    // ---- reduce rowsums across the quad, write 1/rowsum ----
    lsum0 += __shfl_xor_sync(0xffffffffu, lsum0, 1);
    lsum0 += __shfl_xor_sync(0xffffffffu, lsum0, 2);
    lsum1 += __shfl_xor_sync(0xffffffffu, lsum1, 1);
    lsum1 += __shfl_xor_sync(0xffffffffu, lsum1, 2);
    if (t == 0) {
        g_inv[qrow_g]     = 1.0f / lsum0;
        g_inv[qrow_g + 8] = 1.0f / lsum1;
    }
}

// ============================================================================
// Kernel B: attn[i] *= 1/rowsum (float4 grid-stride) — measured 75us @80% DRAM
// ============================================================================
__global__ void __launch_bounds__(256)
norm_kernel(float* __restrict__ attn) {
    const size_t n4 = (size_t)BB * SQ * SQ / 4;       // 16,777,216 float4
    const size_t stride = (size_t)gridDim.x * 256;
    for (size_t i = (size_t)blockIdx.x * 256 + threadIdx.x; i < n4; i += stride) {
        float inv = g_inv[i >> 9];                     // 512 float4 per row
        float4 v = ((const float4*)attn)[i];
        v.x *= inv; v.y *= inv; v.z *= inv; v.w *= inv;
        ((float4*)attn)[i] = v;
    }
}

// ============================================================================
// Kernel C: O = E @ V (E normalized unless scale_inv). grid (16,16), 256 thr,
// 2 CTAs/SM, single wave. 64 k-tiles of 32 kpos, double-buffered cp.async.
// E A-frags: LDS.32, pitch 36 (conflict-free). V B-frags: LDS.64 from the
// R14-validated transposed pp layout (32-kpos half-tiles are self-contained).
// ============================================================================
__global__ void __launch_bounds__(256, 2)
pv_kernel(const float* __restrict__ Eg, float* __restrict__ outg, int scale_inv) {
    extern __shared__ char smem[];
    const uint32_t sb = smem_u32(smem);

    const int tid = threadIdx.x, wid = tid >> 5, lane = tid & 31;
    const int g = lane >> 2, t = lane & 3;
    const int qt = blockIdx.x, b = blockIdx.y;

    auto issue_prefetch = [&](int kt, int p) {
        const char* esrc = (const char*)(Eg + ((size_t)(b * SQ + qt * 128)) * SQ
                                            + (size_t)kt * 32);
        const uint32_t eb = sb + C_OFF_E + p * 18432;
        #pragma unroll
        for (int j = 0; j < 4; j++) {
            int ci = tid + j * 256;                  // 1024 chunks: 128 rows x 8
            int r = ci >> 3, q = ci & 7;
            cp16(eb + r * 144 + q * 16, esrc + (size_t)r * (SQ * 4) + q * 16);
        }
        const char* vsrc = (const char*)(g_V + ((size_t)b * 32 + (kt >> 1)) * 8192
                                             + (kt & 1) * 32);
        const uint32_t vb = sb + C_OFF_V + p * 16384;
        #pragma unroll
        for (int j = 0; j < 4; j++) {
            int ci = tid + j * 256;                  // 1024 chunks: 128 d x 8
            int d = ci >> 3, q = ci & 7;
            cp16(vb + d * 128 + q * 16, vsrc + (size_t)d * 256 + q * 16);
        }
        CP_COMMIT();
    };
    issue_prefetch(0, 0);

    float o[16][4];
    #pragma unroll
    for (int nt = 0; nt < 16; nt++) { o[nt][0] = o[nt][1] = o[nt][2] = o[nt][3] = 0.0f; }

    const int qb = wid * 16;
    const size_t qrow_g = (size_t)(b * SQ + qt * 128) + qb + g;
    const uint32_t xg = (uint32_t)(g & 3) << 3;

    for (int kt = 0; kt < 64; kt++) {
        const int p = kt & 1;
        const float* const Es = (const float*)(smem + C_OFF_E + p * 18432);
        const uint32_t* const Vs = (const uint32_t*)(smem + C_OFF_V + p * 16384);

        CP_WAIT0();
        __syncthreads();
        if (kt < 63) issue_prefetch(kt + 1, p ^ 1);

        #pragma unroll
        for (int ks2 = 0; ks2 < 4; ks2++) {
            const int col = 8 * ks2 + t;
            const uint32_t a0 = f2tf32(Es[(qb + g) * 36 + col]);
            const uint32_t a1 = f2tf32(Es[(qb + 8 + g) * 36 + col]);
            const uint32_t a2 = f2tf32(Es[(qb + g) * 36 + col + 4]);
            const uint32_t a3 = f2tf32(Es[(qb + 8 + g) * 36 + col + 4]);
            const uint32_t pk = ((uint32_t)(8 * ks2 + 2 * t)) ^ xg;
            #pragma unroll
            for (int nt = 0; nt < 16; nt++) {
                const uint2 bb = *(const uint2*)(Vs + (8 * nt + g) * 32 + pk);
                mma_tf32(o[nt][0], o[nt][1], o[nt][2], o[nt][3],
                         a0, a1, a2, a3, bb.x, bb.y);
            }
        }
    }

    float inv0 = 1.0f, inv1 = 1.0f;
    if (scale_inv) { inv0 = g_inv[qrow_g]; inv1 = g_inv[qrow_g + 8]; }

    float* orow0 = outg + qrow_g * DD;
    float* orow1 = orow0 + 8 * (size_t)DD;
    #pragma unroll
    for (int nt = 0; nt < 16; nt++) {
        const int cb = 8 * nt + 2 * t;
        *(float2*)(orow0 + cb) = make_float2(o[nt][0] * inv0, o[nt][1] * inv0);
        *(float2*)(orow1 + cb) = make_float2(o[nt][2] * inv1, o[nt][3] * inv1);
    }
}

// ============================================================================
// Launch
// ============================================================================
__global__ void get_e_fallback(float** out) { *out = g_E; }

extern "C" void kernel_launch(void* const* d_in, const int* in_sizes, int n_in,
                              void* d_out, int out_size) {
    const float* Q = (const float*)d_in[0];
    const float* K = (const float*)d_in[1];
    const float* V = (const float*)d_in[2];
    const void*  M = d_in[3];

    float* out = (float*)d_out;
    const long long out_elems  = (long long)BB * SQ * DD;              // 4,194,304
    const long long attn_elems = (long long)BB * SQ * SQ;              // 67,108,864
    int has_attn = ((long long)out_size >= out_elems + attn_elems) ? 1 : 0;
    float* attn = out + out_elems;

    // E destination: attn slice when present, else device-global scratch.
    float* e_dst = attn;
    void* e_sym = nullptr;
    if (!has_attn) {
        cudaGetSymbolAddress(&e_sym, g_E);
        e_dst = (float*)e_sym;
    }

    cudaFuncSetAttribute(qk_kernel,
                         cudaFuncAttributeMaxDynamicSharedMemorySize, A_SMEM);
    cudaFuncSetAttribute(pv_kernel,
                         cudaFuncAttributeMaxDynamicSharedMemorySize, C_SMEM);

    cvt_kernel<<<dim3(512, 2), 256>>>(K, V);
    qk_kernel<<<dim3(SQ / 128, BB), 256, A_SMEM>>>(Q, M, e_dst);
    if (has_attn)
        norm_kernel<<<8192, 256>>>(attn);
    pv_kernel<<<dim3(SQ / 128, BB), 256, C_SMEM>>>(e_dst, out, has_attn ? 0 : 1);
}

// round 17
// speedup vs baseline: 1.7626x; 1.1177x over previous
#include <cuda_runtime.h>
#include <cstdint>
#include <cstddef>

// ============================================================================
// Problem constants
// ============================================================================
static constexpr int BB  = 16;
static constexpr int SQ  = 2048;
static constexpr int DD  = 128;
static constexpr float QK_SCALE = 0.08838834764831845f;  // 1/sqrt(128)

// Kernel A SMEM (bytes), 2 CTAs/SM, 256 threads:
// Q : 128 rows x 128 words, pair-permuted + swizzled (64 KB), staged once
// K : double-buffered 32 kpos x 128 d word tiles, pp + swizzle (16 KB each)
// M : double-buffered mask tiles, 128 rows x 32 byte-cols, 48B pitch (6 KB)
static constexpr int A_OFF_Q = 0;
static constexpr int A_OFF_K = 65536;    // + p*16384
static constexpr int A_OFF_M = 98304;    // + p*6144
static constexpr int A_SMEM  = 110592;

// Kernel C SMEM (bytes), 2 CTAs/SM, 256 threads:
// E : double-buffered 128 q x 32 kpos fp32, pitch 36 words (18 KB each)
// V : double-buffered 128 d x 32 kpos tf32 half-tiles (16 KB each)
// I : 128 floats of 1/rowsum (512 B)
static constexpr int C_OFF_E = 0;        // + p*18432
static constexpr int C_OFF_V = 36864;    // + p*16384
static constexpr int C_OFF_I = 69632;
static constexpr int C_SMEM  = 70144;

// ============================================================================
// Device globals (no dynamic allocation allowed)
// ============================================================================
__device__ float    g_inv[BB * SQ];
__device__ uint32_t g_K[(size_t)BB * SQ * DD];   // tf32 [kpos][d], pp + swizzle
__device__ uint32_t g_V[(size_t)BB * SQ * DD];   // tf32 per-64-tile [d][kpos], pp + swizzle
__device__ float    g_E[(size_t)BB * SQ * SQ];   // fallback E when attn not in output

// ============================================================================
// Helpers
// ============================================================================
__device__ __forceinline__ uint32_t smem_u32(const void* p) {
    uint32_t a;
    asm("{ .reg .u64 t; cvta.to.shared.u64 t, %1; cvt.u32.u64 %0, t; }"
        : "=r"(a) : "l"(p));
    return a;
}

__device__ __forceinline__ uint32_t f2tf32(float f) {
    uint32_t r;
    asm("cvt.rna.tf32.f32 %0, %1;" : "=r"(r) : "f"(f));
    return r;
}

__device__ __forceinline__ void cp16(uint32_t dst, const void* src) {
    asm volatile("cp.async.cg.shared.global [%0], [%1], 16;"
                 :: "r"(dst), "l"(src) : "memory");
}
#define CP_COMMIT() asm volatile("cp.async.commit_group;" ::: "memory")
#define CP_WAIT0()  asm volatile("cp.async.wait_group 0;" ::: "memory")

__device__ __forceinline__ void mma_tf32(float& c0, float& c1, float& c2, float& c3,
                                         uint32_t a0, uint32_t a1, uint32_t a2, uint32_t a3,
                                         uint32_t b0, uint32_t b1) {
    asm volatile(
        "mma.sync.aligned.m16n8k8.row.col.f32.tf32.tf32.f32 "
        "{%0,%1,%2,%3}, {%4,%5,%6,%7}, {%8,%9}, {%0,%1,%2,%3};"
        : "+f"(c0), "+f"(c1), "+f"(c2), "+f"(c3)
        : "r"(a0), "r"(a1), "r"(a2), "r"(a3), "r"(b0), "r"(b1));
}

// ============================================================================
// Kernel 0: K/V fp32 -> tf32 pre-conversion (validated R13/R14 layouts).
// K: word = kpos*128 + (pp(c) ^ ((kpos&3)<<3)), pp: (0,4,1,5,2,6,3,7)
// Vt: per 64-kpos tile: word = d*64 + (pp(kp) ^ ((d&3)<<3))
// ============================================================================
__global__ void __launch_bounds__(256)
cvt_kernel(const float* __restrict__ Kg, const float* __restrict__ Vg) {
    const int tid = threadIdx.x;
    const size_t base = (size_t)blockIdx.x * 8192;
    if (blockIdx.y == 1) {
        #pragma unroll
        for (int i = 0; i < 8; i++) {
            uint32_t w = (tid + i * 256) * 4;               // dest word offset
            uint32_t r = (w >> 7) & 3;                      // kpos & 3
            uint32_t dcol = w & 127;
            uint32_t gL = (((dcol >> 3) ^ r) << 3);         // logical 8-col group
            const float* src = Kg + base + (w & ~127u) + gL;
            uint4 o;
            if (((dcol >> 2) & 1) == 0) {
                o.x = f2tf32(src[0]); o.y = f2tf32(src[4]);
                o.z = f2tf32(src[1]); o.w = f2tf32(src[5]);
            } else {
                o.x = f2tf32(src[2]); o.y = f2tf32(src[6]);
                o.z = f2tf32(src[3]); o.w = f2tf32(src[7]);
            }
            *(uint4*)(g_K + base + w) = o;
        }
    } else {
        __shared__ uint32_t s[64 * 129];                    // [kp][d], pitch 129
        #pragma unroll
        for (int i = 0; i < 8; i++) {
            int i4 = tid + i * 256;                         // 2048 float4
            int kp = i4 >> 5, d4 = i4 & 31;
            float4 v = ((const float4*)(Vg + base))[i4];
            uint32_t* ps = s + kp * 129 + d4 * 4;
            ps[0] = f2tf32(v.x); ps[1] = f2tf32(v.y);
            ps[2] = f2tf32(v.z); ps[3] = f2tf32(v.w);
        }
        __syncthreads();
        #pragma unroll
        for (int i = 0; i < 32; i++) {
            int w = tid + i * 256;                          // 0..8191
            int d = w >> 6, colout = w & 63;
            int ppk = colout ^ ((d & 3) << 3);
            int kp = (ppk & ~7) | ((ppk & 7) >> 1) | ((ppk & 1) << 2);
            g_V[base + w] = s[kp * 129 + d];
        }
    }
}

// ============================================================================
// Kernel A: QK^T + softmax numerator. grid (16,16), 256 thr, 2 CTAs/SM,
// single wave. 64 k-tiles of 32 kpos, cp.async double-buffered.
// Writes UNNORMALIZED exp(scores) to Eg (default cache policy, so the tail
// stays L2-warm for pv) and 1/rowsum to g_inv.
// ============================================================================
__global__ void __launch_bounds__(256, 2)
qk_kernel(const float* __restrict__ Qg, const void* __restrict__ maskg,
          float* __restrict__ Eg) {
    extern __shared__ char smem[];
    const uint32_t sb = smem_u32(smem);
    uint32_t* const Qs = (uint32_t*)(smem + A_OFF_Q);

    const int tid = threadIdx.x, wid = tid >> 5, lane = tid & 31;
    const int g = lane >> 2, t = lane & 3;
    const int qt = blockIdx.x, b = blockIdx.y;

    // ---- inline mask dtype detection (bool/uint8 vs int32) ----
    int bad = 0;
    { uint32_t w = ((const uint32_t*)maskg)[tid]; if (w & 0xffffff00u) bad = 1; }
    const int m32 = __syncthreads_or(bad) ? 0 : 1;

    const size_t mask_row0 = (size_t)(b * SQ + qt * 128);

    auto issue_prefetch = [&](int kt, int p) {
        const char* ksrc = (const char*)(g_K + (size_t)b * (SQ * DD) + kt * 4096);
        const uint32_t kb = sb + A_OFF_K + p * 16384;
        #pragma unroll
        for (int j = 0; j < 4; j++) {
            int ci = tid + j * 256;                  // 1024 16B-chunks
            cp16(kb + ci * 16, ksrc + ci * 16);
        }
        if (!m32) {
            const uint8_t* msrc = (const uint8_t*)maskg + mask_row0 * SQ + (size_t)kt * 32;
            const uint32_t mb = sb + A_OFF_M + p * 6144;
            int r = tid >> 1, h = tid & 1;           // 128 rows x 2 chunks
            cp16(mb + r * 48 + h * 16, msrc + (size_t)r * SQ + h * 16);
        }
        CP_COMMIT();
    };
    issue_prefetch(0, 0);

    // ---- stage Q once (fp32 -> tf32, pair-permuted + swizzled) ----
    {
        const float* qsrc = Qg + ((size_t)(b * SQ + qt * 128)) * DD;
        #pragma unroll
        for (int i = 0; i < 16; i++) {
            int idx = tid + i * 256;
            int r = idx >> 5, f = idx & 31;
            float4 v = ((const float4*)(qsrc + (size_t)r * DD))[f];
            uint32_t xr = (r & 3) << 3;
            #pragma unroll
            for (int j = 0; j < 4; j++) {
                int c = 4 * f + j;
                uint32_t pp = (c & ~7) | ((c & 3) << 1) | ((c >> 2) & 1);
                Qs[r * 128 + (pp ^ xr)] = f2tf32(((const float*)&v)[j]);
            }
        }
    }

    float lsum0 = 0.0f, lsum1 = 0.0f;
    const int qrow_l = wid * 16 + g;
    const size_t qrow_g = (size_t)(b * SQ + qt * 128) + qrow_l;
    const uint32_t xg = (uint32_t)(g & 3) << 3;

    for (int kt = 0; kt < 64; kt++) {
        const int p = kt & 1;
        uint32_t* const Ks = (uint32_t*)(smem + A_OFF_K + p * 16384);
        uint8_t*  const Ms = (uint8_t*)(smem + A_OFF_M + p * 6144);

        CP_WAIT0();
        __syncthreads();
        if (kt < 63) issue_prefetch(kt + 1, p ^ 1);

        if (m32) {
            const int* msrc = (const int*)maskg;
            #pragma unroll
            for (int i = 0; i < 4; i++) {
                int lin = tid + i * 256;               // 1024 groups of 4 ints
                int r = lin >> 3, gi = lin & 7;
                size_t off = (mask_row0 + r) * SQ + kt * 32 + 4 * gi;
                uint4 x = *(const uint4*)(msrc + off);
                uint32_t packed = (x.x & 0xffu) | ((x.y & 0xffu) << 8) |
                                  ((x.z & 0xffu) << 16) | ((x.w & 0xffu) << 24);
                *(uint32_t*)(Ms + r * 48 + 4 * gi) = packed;
            }
            __syncthreads();
        }

        // ---- QK^T: scores C (16 rows x 32 kpos per warp), LDS.64 frags ----
        float c[4][4];
        #pragma unroll
        for (int nt = 0; nt < 4; nt++) { c[nt][0] = c[nt][1] = c[nt][2] = c[nt][3] = 0.0f; }

        #pragma unroll
        for (int ks = 0; ks < 16; ks++) {
            const uint32_t pc = ((uint32_t)(8 * ks + 2 * t)) ^ xg;
            const uint2 a01 = *(const uint2*)(Qs + qrow_l * 128 + pc);
            const uint2 a23 = *(const uint2*)(Qs + (qrow_l + 8) * 128 + pc);
            #pragma unroll
            for (int nt = 0; nt < 4; nt++) {
                const uint2 bb = *(const uint2*)(Ks + (8 * nt + g) * 128 + pc);
                mma_tf32(c[nt][0], c[nt][1], c[nt][2], c[nt][3],
                         a01.x, a23.x, a01.y, a23.y, bb.x, bb.y);
            }
        }

        // ---- softmax numerator: mask, exp, rowsum, E write ----
        float* arow0 = Eg + qrow_g * SQ + kt * 32;
        float* arow1 = arow0 + 8 * (size_t)SQ;
        const uint8_t* mrow0 = Ms + qrow_l * 48;
        const uint8_t* mrow1 = Ms + (qrow_l + 8) * 48;
        #pragma unroll
        for (int nt = 0; nt < 4; nt++) {
            const int cb = 8 * nt + 2 * t;
            uint32_t m0 = *(const uint16_t*)(mrow0 + cb);
            uint32_t m1 = *(const uint16_t*)(mrow1 + cb);
            float e0 = (m0 & 0xffu) ? 0.0f : __expf(c[nt][0] * QK_SCALE);
            float e1 = (m0 >> 8)    ? 0.0f : __expf(c[nt][1] * QK_SCALE);
            float e2 = (m1 & 0xffu) ? 0.0f : __expf(c[nt][2] * QK_SCALE);
            float e3 = (m1 >> 8)    ? 0.0f : __expf(c[nt][3] * QK_SCALE);
            lsum0 += e0 + e1;
            lsum1 += e2 + e3;
            *(float2*)(arow0 + cb) = make_float2(e0, e1);
            *(float2*)(arow1 + cb) = make_float2(e2, e3);
        }
    }

    // ---- reduce rowsums across the quad, write 1/rowsum ----
    lsum0 += __shfl_xor_sync(0xffffffffu, lsum0, 1);
    lsum0 += __shfl_xor_sync(0xffffffffu, lsum0, 2);
    lsum1 += __shfl_xor_sync(0xffffffffu, lsum1, 1);
    lsum1 += __shfl_xor_sync(0xffffffffu, lsum1, 2);
    if (t == 0) {
        g_inv[qrow_g]     = 1.0f / lsum0;
        g_inv[qrow_g + 8] = 1.0f / lsum1;
    }
}

// ============================================================================
// Kernel C: O = (E @ V) * inv, and (fused) attn = E * inv written back from
// the staged tiles. grid (16,16), 256 thr, 2 CTAs/SM, single wave.
// 64 k-tiles of 32 kpos, double-buffered cp.async. E A-frags: LDS.32,
// pitch 36 (conflict-free). V B-frags: LDS.64 (R14-validated layout).
// ============================================================================
__global__ void __launch_bounds__(256, 2)
pv_kernel(float* __restrict__ Eg, float* __restrict__ outg, int write_attn) {
    extern __shared__ char smem[];
    const uint32_t sb = smem_u32(smem);
    float* const sInv = (float*)(smem + C_OFF_I);

    const int tid = threadIdx.x, wid = tid >> 5, lane = tid & 31;
    const int g = lane >> 2, t = lane & 3;
    const int qt = blockIdx.x, b = blockIdx.y;
    const size_t rowbase = (size_t)(b * SQ + qt * 128);

    auto issue_prefetch = [&](int kt, int p) {
        const char* esrc = (const char*)(Eg + rowbase * SQ + (size_t)kt * 32);
        const uint32_t eb = sb + C_OFF_E + p * 18432;
        #pragma unroll
        for (int j = 0; j < 4; j++) {
            int ci = tid + j * 256;                  // 1024 chunks: 128 rows x 8
            int r = ci >> 3, q = ci & 7;
            cp16(eb + r * 144 + q * 16, esrc + (size_t)r * (SQ * 4) + q * 16);
        }
        const char* vsrc = (const char*)(g_V + ((size_t)b * 32 + (kt >> 1)) * 8192
                                             + (kt & 1) * 32);
        const uint32_t vb = sb + C_OFF_V + p * 16384;
        #pragma unroll
        for (int j = 0; j < 4; j++) {
            int ci = tid + j * 256;                  // 1024 chunks: 128 d x 8
            int d = ci >> 3, q = ci & 7;
            cp16(vb + d * 128 + q * 16, vsrc + (size_t)d * 256 + q * 16);
        }
        CP_COMMIT();
    };
    issue_prefetch(0, 0);

    // stage 1/rowsum for this CTA's 128 rows (visible after first sync)
    if (tid < 128) sInv[tid] = g_inv[rowbase + tid];

    float o[16][4];
    #pragma unroll
    for (int nt = 0; nt < 16; nt++) { o[nt][0] = o[nt][1] = o[nt][2] = o[nt][3] = 0.0f; }

    const int qb = wid * 16;
    const size_t qrow_g = rowbase + qb + g;
    const uint32_t xg = (uint32_t)(g & 3) << 3;

    for (int kt = 0; kt < 64; kt++) {
        const int p = kt & 1;
        const float* const Es = (const float*)(smem + C_OFF_E + p * 18432);
        const uint32_t* const Vs = (const uint32_t*)(smem + C_OFF_V + p * 16384);

        CP_WAIT0();
        __syncthreads();
        if (kt < 63) issue_prefetch(kt + 1, p ^ 1);

        // ---- fused normalization write-back: attn = E * inv (overlaps MMA) ----
        if (write_attn) {
            #pragma unroll
            for (int j = 0; j < 4; j++) {
                int ci = tid + j * 256;              // 1024 float4: 128 rows x 8
                int r = ci >> 3, q = ci & 7;
                float inv = sInv[r];
                float4 v = *(const float4*)(Es + r * 36 + q * 4);
                v.x *= inv; v.y *= inv; v.z *= inv; v.w *= inv;
                __stcs((float4*)(Eg + (rowbase + r) * SQ + kt * 32 + q * 4), v);
            }
        }

        #pragma unroll
        for (int ks2 = 0; ks2 < 4; ks2++) {
            const int col = 8 * ks2 + t;
            const uint32_t a0 = f2tf32(Es[(qb + g) * 36 + col]);
            const uint32_t a1 = f2tf32(Es[(qb + 8 + g) * 36 + col]);
            const uint32_t a2 = f2tf32(Es[(qb + g) * 36 + col + 4]);
            const uint32_t a3 = f2tf32(Es[(qb + 8 + g) * 36 + col + 4]);
            const uint32_t pk = ((uint32_t)(8 * ks2 + 2 * t)) ^ xg;
            #pragma unroll
            for (int nt = 0; nt < 16; nt++) {
                const uint2 bb = *(const uint2*)(Vs + (8 * nt + g) * 32 + pk);
                mma_tf32(o[nt][0], o[nt][1], o[nt][2], o[nt][3],
                         a0, a1, a2, a3, bb.x, bb.y);
            }
        }
    }

    // ---- epilogue: out = O * inv (E was unnormalized) ----
    const float inv0 = sInv[qb + g];
    const float inv1 = sInv[qb + 8 + g];
    float* orow0 = outg + qrow_g * DD;
    float* orow1 = orow0 + 8 * (size_t)DD;
    #pragma unroll
    for (int nt = 0; nt < 16; nt++) {
        const int cb = 8 * nt + 2 * t;
        *(float2*)(orow0 + cb) = make_float2(o[nt][0] * inv0, o[nt][1] * inv0);
        *(float2*)(orow1 + cb) = make_float2(o[nt][2] * inv1, o[nt][3] * inv1);
    }
}

// ============================================================================
// Launch
// ============================================================================
extern "C" void kernel_launch(void* const* d_in, const int* in_sizes, int n_in,
                              void* d_out, int out_size) {
    const float* Q = (const float*)d_in[0];
    const float* K = (const float*)d_in[1];
    const float* V = (const float*)d_in[2];
    const void*  M = d_in[3];

    float* out = (float*)d_out;
    const long long out_elems  = (long long)BB * SQ * DD;              // 4,194,304
    const long long attn_elems = (long long)BB * SQ * SQ;              // 67,108,864
    int has_attn = ((long long)out_size >= out_elems + attn_elems) ? 1 : 0;
    float* attn = out + out_elems;

    // E destination: attn slice when present, else device-global scratch.
    float* e_dst = attn;
    void* e_sym = nullptr;
    if (!has_attn) {
        cudaGetSymbolAddress(&e_sym, g_E);
        e_dst = (float*)e_sym;
    }

    cudaFuncSetAttribute(qk_kernel,
                         cudaFuncAttributeMaxDynamicSharedMemorySize, A_SMEM);
    cudaFuncSetAttribute(pv_kernel,
                         cudaFuncAttributeMaxDynamicSharedMemorySize, C_SMEM);

    cvt_kernel<<<dim3(512, 2), 256>>>(K, V);
    qk_kernel<<<dim3(SQ / 128, BB), 256, A_SMEM>>>(Q, M, e_dst);
    pv_kernel<<<dim3(SQ / 128, BB), 256, C_SMEM>>>(e_dst, out, has_attn);
}